// round 9
// baseline (speedup 1.0000x reference)
#include <cuda_runtime.h>
#include <cuda_bf16.h>
#include <math.h>
#include <stdint.h>

#define N_TOT 2048
#define T_SEQ 70
#define HID   230
#define DIN   60
#define EMB_W 50
#define NBAG  64
#define BAGSZ 32
#define NREL  100

// GRU step: M=128, N=96 (32j x 3 gates), K=320 (2 emb chunks + 8 h chunks of 32)
// stage: A_hi[128*64B] A_lo B_hi[96*64B] B_lo, XOR-swizzled 64B rows (pre-swizzled in gmem)
#define NTHREADS 384
#define STAGE_B  28672
#define A_LO_OFF 8192
#define B_HI_OFF 16384
#define DUMP_OFF (3 * STAGE_B)            // 86016
#define SMEM_DYN (DUMP_OFF + 32 * 132 * 4) // 102912

// ---------------- device scratch (all MMA staging pre-swizzled, chunk-major) ----
__device__ __align__(128) __nv_bfloat16 g_Wt[(size_t)2 * 8 * 2 * 10 * 96 * 32]; // [dir][jt][part][chunk][6KB swz]
__device__ __align__(128) __nv_bfloat16 g_embsp[(size_t)T_SEQ * 2 * 2 * N_TOT * 32]; // [t][part][chunk2][2048*64B swz]
__device__ __align__(128) __nv_bfloat16 g_hbf[(size_t)2 * 2 * 2 * 8 * N_TOT * 32];   // [buf][dir][part][chunk8][2048*64B swz]
__device__ float g_hT[(size_t)2 * 2 * 256 * N_TOT];                               // [buf][dir][j][n]
__device__ float g_tup[(size_t)2 * T_SEQ * N_TOT * HID];                          // [dir][t][n][j]
__device__ float g_repre[N_TOT * HID];
__device__ float g_sen_s[NBAG * HID];
__device__ float g_loss_part[NBAG];

// ---------------- ptx helpers ----------------
__device__ __forceinline__ uint32_t smem_u32(const void *p) {
    uint32_t a;
    asm("{ .reg .u64 t; cvta.to.shared.u64 t, %1; cvt.u32.u64 %0, t; }" : "=r"(a) : "l"(p));
    return a;
}
#define BULK_G2S(dst, src, bytes, mbar)                                               \
    asm volatile(                                                                     \
        "cp.async.bulk.shared::cluster.global.mbarrier::complete_tx::bytes "          \
        "[%0], [%1], %2, [%3];"                                                       \
        :: "r"((uint32_t)(dst)), "l"(src), "r"((uint32_t)(bytes)),                    \
           "r"((uint32_t)(mbar)) : "memory")
#define MBARRIER_INIT(mb, cnt) \
    asm volatile("mbarrier.init.shared.b64 [%0], %1;" :: "r"((uint32_t)(mb)), "r"((uint32_t)(cnt)) : "memory")
#define MBARRIER_EXPECT_TX(mb, tx) \
    asm volatile("mbarrier.arrive.expect_tx.shared.b64 _, [%0], %1;" :: "r"((uint32_t)(mb)), "r"((uint32_t)(tx)) : "memory")
#define MBARRIER_ARRIVE(mb) \
    asm volatile("mbarrier.arrive.shared.b64 _, [%0];" :: "r"((uint32_t)(mb)) : "memory")
#define FENCE_ASYNC_SHARED() asm volatile("fence.proxy.async.shared::cta;" ::: "memory")
#define MBARRIER_WAIT_PARITY(mb, ph) do {                                             \
    uint32_t _m = (uint32_t)(mb); uint32_t _p = (uint32_t)(ph); uint32_t _d;          \
    asm volatile("{\n\t.reg .pred p;\n\t"                                             \
        "mbarrier.try_wait.parity.acquire.cta.shared::cta.b64 p, [%1], %2;\n\t"       \
        "selp.b32 %0, 1, 0, p;\n\t}" : "=r"(_d) : "r"(_m), "r"(_p) : "memory");       \
    if (!_d) {                                                                        \
        asm volatile("{\n\t.reg .pred P1;\n\t"                                        \
            "WL_%=:\n\t"                                                              \
            "mbarrier.try_wait.parity.acquire.cta.shared::cta.b64 P1, [%0], %1, 0x989680;\n\t" \
            "@P1 bra.uni WD_%=;\n\tbra.uni WL_%=;\n\tWD_%=:\n\t}"                     \
            :: "r"(_m), "r"(_p) : "memory");                                          \
    }                                                                                 \
} while (0)
#define LDSM4(r, a)                                                                   \
    asm volatile("ldmatrix.sync.aligned.m8n8.x4.shared.b16 {%0,%1,%2,%3}, [%4];"      \
                 : "=r"((r)[0]), "=r"((r)[1]), "=r"((r)[2]), "=r"((r)[3]) : "r"(a))
#define MMA16816(c, a, b0, b1)                                                        \
    asm volatile("mma.sync.aligned.m16n8k16.row.col.f32.bf16.bf16.f32 "               \
                 "{%0,%1,%2,%3},{%4,%5,%6,%7},{%8,%9},{%0,%1,%2,%3};"                 \
                 : "+f"((c)[0]), "+f"((c)[1]), "+f"((c)[2]), "+f"((c)[3])             \
                 : "r"((a)[0]), "r"((a)[1]), "r"((a)[2]), "r"((a)[3]), "r"(b0), "r"(b1))

__device__ __forceinline__ uint32_t pack2(__nv_bfloat16 a, __nv_bfloat16 b) {
    unsigned short ra = *(unsigned short *)&a, rb = *(unsigned short *)&b;
    return (uint32_t)ra | ((uint32_t)rb << 16);
}
// swizzled byte offset: 64B rows, 16B segs permuted within 8-row (512B) blocks
__device__ __forceinline__ uint32_t swz(int row, int seg) {
    return (uint32_t)row * 64u + (uint32_t)((seg ^ ((row >> 1) & 3)) << 4);
}
__device__ __forceinline__ uint32_t swz_elem(int row, int kc) {
    return (swz(row, kc >> 3) + (uint32_t)(kc & 7) * 2u) >> 1;
}

// ---------------- prep kernels ----------------
__global__ void zero_kernel() {
    size_t i = (size_t)blockIdx.x * blockDim.x + threadIdx.x;
    size_t nh = (size_t)2 * 2 * 2 * 8 * N_TOT * 32 / 2;
    if (i < nh) ((uint32_t *)g_hbf)[i] = 0u;
    if (i < (size_t)2 * 2 * 256 * N_TOT) g_hT[i] = 0.f;
}

__global__ void prep_w_kernel(const float *__restrict__ Wihf, const float *__restrict__ Whhf,
                              const float *__restrict__ Wihb, const float *__restrict__ Whhb) {
    int idx = blockIdx.x * blockDim.x + threadIdx.x;
    if (idx >= 2 * 8 * 10 * 96 * 32) return;
    int kc = idx & 31;
    int r = (idx >> 5) % 96;
    int rest = idx / (96 * 32);
    int c = rest % 10;
    int jt = (rest / 10) & 7;
    int dir = rest / 80;
    const float *Wih = dir ? Wihb : Wihf;
    const float *Whh = dir ? Whhb : Whhf;
    int j = jt * 32 + r / 3;
    int g = r % 3;
    float v = 0.f;
    if (j < HID) {
        if (c < 2) {
            int k = c * 32 + kc;
            if (k < DIN) v = Wih[(g * HID + j) * DIN + k];
        } else {
            int kh = (c - 2) * 32 + kc;
            if (kh < HID) v = Whh[(g * HID + j) * HID + kh];
        }
    }
    __nv_bfloat16 hi = __float2bfloat16(v);
    __nv_bfloat16 lo = __float2bfloat16(v - __bfloat162float(hi));
    uint32_t off = swz_elem(r, kc);
    size_t b0 = (((size_t)(dir * 8 + jt) * 2 + 0) * 10 + c) * (96 * 32);
    size_t b1 = (((size_t)(dir * 8 + jt) * 2 + 1) * 10 + c) * (96 * 32);
    g_Wt[b0 + off] = hi;
    g_Wt[b1 + off] = lo;
}

__global__ void gather_kernel(const int *__restrict__ sent, const int *__restrict__ p1,
                              const int *__restrict__ p2, const float *__restrict__ wemb,
                              const float *__restrict__ p1t, const float *__restrict__ p2t) {
    size_t idx = (size_t)blockIdx.x * blockDim.x + threadIdx.x;
    if (idx >= (size_t)N_TOT * T_SEQ * 64) return;
    int k = (int)(idx & 63);
    size_t nt = idx >> 6;
    int t = (int)(nt % T_SEQ);
    int n = (int)(nt / T_SEQ);
    float v = 0.f;
    if (k < EMB_W) v = wemb[(size_t)sent[n * T_SEQ + t] * EMB_W + k];
    else if (k < EMB_W + 5) v = p1t[p1[n * T_SEQ + t] * 5 + (k - EMB_W)];
    else if (k < DIN) v = p2t[p2[n * T_SEQ + t] * 5 + (k - EMB_W - 5)];
    __nv_bfloat16 hi = __float2bfloat16(v);
    __nv_bfloat16 lo = __float2bfloat16(v - __bfloat162float(hi));
    int chunk = k >> 5, kc = k & 31;
    uint32_t off = swz_elem(n, kc);
    size_t b0 = (((size_t)t * 2 + 0) * 2 + chunk) * (N_TOT * 32);
    size_t b1 = (((size_t)t * 2 + 1) * 2 + chunk) * (N_TOT * 32);
    g_embsp[b0 + off] = hi;
    g_embsp[b1 + off] = lo;
}

// ---------------- GRU step (bf16 3-pass, bulk pipeline, sw-pipelined frags) ----
__global__ void __launch_bounds__(NTHREADS, 2) gru_step_kernel(
    int s,
    const float *__restrict__ bihf, const float *__restrict__ bhhf,
    const float *__restrict__ bihb, const float *__restrict__ bhhb) {
    extern __shared__ char dsm[];
    const int dir = blockIdx.z;
    const int t = dir ? (T_SEQ - 1 - s) : s;
    const int n0 = blockIdx.x * 128;
    const int jt = blockIdx.y;
    const int tid = threadIdx.x;
    const int lane = tid & 31, wid = tid >> 5;
    const int warpM = wid & 3, warpN = wid >> 2;
    const int bufi = s & 1, bufo = (s + 1) & 1;
    const float *bih = dir ? bihb : bihf;
    const float *bhh = dir ? bhhb : bhhf;

    const uint32_t base = smem_u32(dsm);
    float *dumpIN = (float *)(dsm + DUMP_OFF);
    __shared__ float bs[4][32];
    __shared__ __align__(8) unsigned long long mbar[6];   // full[3], empty[3]
    const uint32_t mbF = smem_u32(mbar);
    const uint32_t mbE = mbF + 24;

    if (tid < 32) {
        int j = jt * 32 + tid;
        bool ok = j < HID;
        bs[0][tid] = ok ? (bih[j] + bhh[j]) : 0.f;
        bs[1][tid] = ok ? (bih[HID + j] + bhh[HID + j]) : 0.f;
        bs[2][tid] = ok ? bih[2 * HID + j] : 0.f;
        bs[3][tid] = ok ? bhh[2 * HID + j] : 0.f;
    }
    if (tid == 0) {
        MBARRIER_INIT(mbF, 1);
        MBARRIER_INIT(mbF + 8, 1);
        MBARRIER_INIT(mbF + 16, 1);
        MBARRIER_INIT(mbE, 12);
        MBARRIER_INIT(mbE + 8, 12);
        MBARRIER_INIT(mbE + 16, 12);
        FENCE_ASYNC_SHARED();
    }
    __syncthreads();

    const __nv_bfloat16 *embp = g_embsp + (size_t)t * 2 * 2 * N_TOT * 32 + (size_t)n0 * 32;
    const __nv_bfloat16 *hbfp = g_hbf + (size_t)((bufi * 2 + dir) * 2) * 8 * N_TOT * 32 + (size_t)n0 * 32;
    const __nv_bfloat16 *wbase = g_Wt + (size_t)(dir * 8 + jt) * 2 * 10 * (96 * 32);

    auto arm = [&](int k) {
        if (k >= 3) MBARRIER_WAIT_PARITY(mbE + (uint32_t)(k % 3) * 8, ((k / 3) + 1) & 1);
        uint32_t st = base + (uint32_t)(k % 3) * STAGE_B;
        uint32_t mb = mbF + (uint32_t)(k % 3) * 8;
        MBARRIER_EXPECT_TX(mb, STAGE_B);
#pragma unroll
        for (int part = 0; part < 2; part++) {
            const __nv_bfloat16 *Ap = (k < 2)
                ? embp + ((size_t)part * 2 + k) * (N_TOT * 32)
                : hbfp + ((size_t)part * 8 + (k - 2)) * (N_TOT * 32);
            BULK_G2S(st + part * A_LO_OFF, Ap, 8192, mb);
            const __nv_bfloat16 *Bp = wbase + ((size_t)part * 10 + k) * (96 * 32);
            BULK_G2S(st + B_HI_OFF + part * 6144, Bp, 6144, mb);
        }
    };

    if (tid == 0) { arm(0); arm(1); arm(2); }

    float acc[2][4][4];
#pragma unroll
    for (int mi = 0; mi < 2; mi++)
#pragma unroll
        for (int ni = 0; ni < 4; ni++)
#pragma unroll
            for (int q = 0; q < 4; q++) acc[mi][ni][q] = 0.f;

    const int laneR = lane & 15;
    const int laneHi = lane >> 4;
    const int gr = lane >> 2, lc = lane & 3;

    // double-buffered fragment registers
    uint32_t ah[2][2][4], al[2][2][4], bh[2][2][4], bl[2][2][4];

    auto ldsm_stage = [&](int buf, int c, int ks) {
        uint32_t sA = base + (uint32_t)(c % 3) * STAGE_B;
        uint32_t sB = sA + B_HI_OFF;
#pragma unroll
        for (int mi = 0; mi < 2; mi++) {
            int row = warpM * 32 + mi * 16 + laneR;
            uint32_t off = swz(row, ks * 2 + laneHi);
            LDSM4(ah[buf][mi], sA + off);
            LDSM4(al[buf][mi], sA + A_LO_OFF + off);
        }
#pragma unroll
        for (int np = 0; np < 2; np++) {
            int row = warpN * 32 + np * 16 + laneR;
            uint32_t off = swz(row, ks * 2 + laneHi);
            LDSM4(bh[buf][np], sB + off);
            LDSM4(bl[buf][np], sB + 6144 + off);
        }
    };

    auto mma_stage = [&](int buf) {
#pragma unroll
        for (int np = 0; np < 2; np++)
#pragma unroll
            for (int pass = 0; pass < 3; pass++) {
                const uint32_t(*aa)[4] = (pass == 2) ? al[buf] : ah[buf];
                const uint32_t *bb = (pass == 1) ? bl[buf][np] : bh[buf][np];
#pragma unroll
                for (int mi = 0; mi < 2; mi++) {
                    MMA16816(acc[mi][np * 2], aa[mi], bb[0], bb[2]);
                    MMA16816(acc[mi][np * 2 + 1], aa[mi], bb[1], bb[3]);
                }
            }
    };

    // 20 ks-stages, fragment prefetch interleaved with MMAs
    MBARRIER_WAIT_PARITY(mbF, 0);
    ldsm_stage(0, 0, 0);
#pragma unroll
    for (int g = 0; g < 20; g++) {
        const int c = g >> 1, ks = g & 1;
        if (g < 19) {
            const int gn = g + 1, cn = gn >> 1, ksn = gn & 1;
            if (ksn == 0) MBARRIER_WAIT_PARITY(mbF + (uint32_t)(cn % 3) * 8, (cn / 3) & 1);
            ldsm_stage(gn & 1, cn, ksn);
        }
        mma_stage(g & 1);
        if (ks == 1) {
            if (lane == 0) MBARRIER_ARRIVE(mbE + (uint32_t)(c % 3) * 8);
            if (tid == 0 && c + 3 < 10) arm(c + 3);
        }
        if (g == 3) {
            // emb phase done: move i_n slots (col%3==2) to dumpIN, zero them
#pragma unroll
            for (int mi = 0; mi < 2; mi++)
#pragma unroll
                for (int ni = 0; ni < 4; ni++)
#pragma unroll
                    for (int b = 0; b < 2; b++) {
                        int col = warpN * 32 + ni * 8 + lc * 2 + b;
                        if (col % 3 == 2) {
                            int jl = col / 3;
                            int m0 = warpM * 32 + mi * 16 + gr;
                            dumpIN[jl * 132 + m0] = acc[mi][ni][b];
                            dumpIN[jl * 132 + m0 + 8] = acc[mi][ni][b + 2];
                            acc[mi][ni][b] = 0.f;
                            acc[mi][ni][b + 2] = 0.f;
                        }
                    }
        }
    }

    __syncthreads();   // all warps done with stages; reuse for D staging
    float *D2 = (float *)dsm;   // [96 col][132]
#pragma unroll
    for (int mi = 0; mi < 2; mi++)
#pragma unroll
        for (int ni = 0; ni < 4; ni++) {
            int col0 = warpN * 32 + ni * 8 + lc * 2;
            int m0 = warpM * 32 + mi * 16 + gr;
            D2[col0 * 132 + m0] = acc[mi][ni][0];
            D2[(col0 + 1) * 132 + m0] = acc[mi][ni][1];
            D2[col0 * 132 + m0 + 8] = acc[mi][ni][2];
            D2[(col0 + 1) * 132 + m0 + 8] = acc[mi][ni][3];
        }
    __syncthreads();

    // gates: 256 work items (32 jl x 8 nsegs of 16)
    if (tid < 256) {
        int jl = tid >> 3, nseg = tid & 7;
        int j = jt * 32 + jl;
        int nb = nseg * 16;
        float br = bs[0][jl], bz = bs[1][jl], bin = bs[2][jl], bhn = bs[3][jl];
        const float4 *holdp = (const float4 *)(g_hT + ((size_t)(bufi * 2 + dir) * 256 + j) * N_TOT + n0 + nb);
        float4 *hnewp = (float4 *)(g_hT + ((size_t)(bufo * 2 + dir) * 256 + j) * N_TOT + n0 + nb);
        const float *Dr = D2 + (jl * 3 + 0) * 132 + nb;
        const float *Dz = D2 + (jl * 3 + 1) * 132 + nb;
        const float *Dn = D2 + (jl * 3 + 2) * 132 + nb;
        const float *Di = dumpIN + jl * 132 + nb;
        float hv[16];
#pragma unroll
        for (int v4 = 0; v4 < 4; v4++) {
            float4 hold4 = holdp[v4];
            float ho[4] = {hold4.x, hold4.y, hold4.z, hold4.w};
            float4 out4;
            float *o = (float *)&out4;
#pragma unroll
            for (int q = 0; q < 4; q++) {
                int i = v4 * 4 + q;
                float r = 1.f / (1.f + expf(-(Dr[i] + br)));
                float z = 1.f / (1.f + expf(-(Dz[i] + bz)));
                float nn = tanhf(Di[i] + bin + r * (Dn[i] + bhn));
                float h = (1.f - z) * nn + z * ho[q];
                hv[i] = h;
                o[q] = h;
            }
            hnewp[v4] = out4;
        }
#pragma unroll
        for (int i = 0; i < 16; i++) D2[(jl * 3) * 132 + nb + i] = hv[i];
    }
    __syncthreads();

    // writeout: tup fp32 [n][j]; h bf16 hi/lo chunk-major pre-swizzled; 512 items
    {
        __nv_bfloat16 *hb0 = g_hbf + ((((size_t)(bufo * 2 + dir) * 2 + 0) * 8 + jt) * N_TOT) * 32;
        __nv_bfloat16 *hb1 = g_hbf + ((((size_t)(bufo * 2 + dir) * 2 + 1) * 8 + jt) * N_TOT) * 32;
        float *tupp = g_tup + (((size_t)dir * T_SEQ + t) * N_TOT) * HID;
#pragma unroll
        for (int it = 0; it < 2; it++) {
            int l = it * NTHREADS + tid;
            if (l >= 512) break;
            int nl = l >> 2, seg = l & 3;
            int n = n0 + nl;
            int jb = seg * 8;
            float v[8];
#pragma unroll
            for (int q = 0; q < 8; q++) v[q] = D2[((jb + q) * 3) * 132 + nl];
#pragma unroll
            for (int q = 0; q < 8; q++) {
                int j = jt * 32 + jb + q;
                if (j < HID) tupp[(size_t)n * HID + j] = v[q];
            }
            __nv_bfloat16 hi[8], lo[8];
#pragma unroll
            for (int q = 0; q < 8; q++) {
                hi[q] = __float2bfloat16(v[q]);
                lo[q] = __float2bfloat16(v[q] - __bfloat162float(hi[q]));
            }
            uint4 vh, vl;
            vh.x = pack2(hi[0], hi[1]); vh.y = pack2(hi[2], hi[3]);
            vh.z = pack2(hi[4], hi[5]); vh.w = pack2(hi[6], hi[7]);
            vl.x = pack2(lo[0], lo[1]); vl.y = pack2(lo[2], lo[3]);
            vl.z = pack2(lo[4], lo[5]); vl.w = pack2(lo[6], lo[7]);
            uint32_t off = swz(n, seg);
            *(uint4 *)((char *)hb0 + off) = vh;
            *(uint4 *)((char *)hb1 + off) = vl;
        }
    }
}

// ---------------- word-level attention ----------------
__global__ void __launch_bounds__(256) attn_kernel(const float *__restrict__ att_w) {
    const int n = blockIdx.x;
    const int tid = threadIdx.x;
    __shared__ float xsum[HID];
    __shared__ float red[8];
    __shared__ float s_bc;
    float acc = 0.f, m = -1e30f, denom = 0.f;
    float w = (tid < HID) ? att_w[tid] : 0.f;
    for (int t = 0; t < T_SEQ; t++) {
        if (tid < HID) {
            size_t i0 = (((size_t)0 * T_SEQ + t) * N_TOT + n) * HID + tid;
            size_t i1 = (((size_t)1 * T_SEQ + t) * N_TOT + n) * HID + tid;
            xsum[tid] = g_tup[i0] + g_tup[i1];
        }
        __syncthreads();
        float part = (tid < HID) ? tanhf(xsum[tid]) * w : 0.f;
#pragma unroll
        for (int o = 16; o > 0; o >>= 1) part += __shfl_down_sync(0xffffffffu, part, o);
        if ((tid & 31) == 0) red[tid >> 5] = part;
        __syncthreads();
        if (tid == 0) {
            float sm = 0.f;
#pragma unroll
            for (int q = 0; q < 8; q++) sm += red[q];
            s_bc = sm;
        }
        __syncthreads();
        float st = s_bc;
        float mn = fmaxf(m, st);
        float cc = expf(m - mn), e = expf(st - mn);
        denom = denom * cc + e;
        if (tid < HID) acc = acc * cc + e * xsum[tid];
        m = mn;
        __syncthreads();
    }
    if (tid < HID) g_repre[n * HID + tid] = tanhf(acc / denom);
}

// ---------------- bag attention ----------------
__global__ void __launch_bounds__(256) bag_kernel(const float *__restrict__ sen_a,
                                                  const float *__restrict__ sen_r) {
    const int b = blockIdx.x;
    const int tid = threadIdx.x;
    __shared__ float R[BAGSZ][HID];
    __shared__ float sv[BAGSZ];
    __shared__ float alpha[BAGSZ];
    for (int l = tid; l < BAGSZ * HID; l += 256) {
        int i = l / HID, j = l % HID;
        R[i][j] = g_repre[(b * BAGSZ + i) * HID + j];
    }
    __syncthreads();
    int wid = tid >> 5, lane = tid & 31;
    for (int i = wid; i < BAGSZ; i += 8) {
        float p = 0.f;
        for (int j = lane; j < HID; j += 32) p += R[i][j] * sen_a[j] * sen_r[j];
#pragma unroll
        for (int o = 16; o > 0; o >>= 1) p += __shfl_down_sync(0xffffffffu, p, o);
        if (lane == 0) sv[i] = p;
    }
    __syncthreads();
    if (tid == 0) {
        float mm = -1e30f;
        for (int i = 0; i < BAGSZ; i++) mm = fmaxf(mm, sv[i]);
        float ss = 0.f;
        for (int i = 0; i < BAGSZ; i++) { float e = expf(sv[i] - mm); alpha[i] = e; ss += e; }
        for (int i = 0; i < BAGSZ; i++) alpha[i] /= ss;
    }
    __syncthreads();
    for (int j = tid; j < HID; j += 256) {
        float a = 0.f;
#pragma unroll 4
        for (int i = 0; i < BAGSZ; i++) a += alpha[i] * R[i][j];
        g_sen_s[b * HID + j] = a;
    }
}

// ---------------- logits / prob / bce / acc ----------------
__global__ void __launch_bounds__(128) logits_kernel(const float *__restrict__ rel,
                                                     const float *__restrict__ sen_d,
                                                     const float *__restrict__ y,
                                                     float *__restrict__ out) {
    const int b = blockIdx.x;
    const int tid = threadIdx.x;
    __shared__ float ss[HID];
    __shared__ float lg[NREL];
    __shared__ float mmax;
    __shared__ int amax;
    __shared__ float dsum;
    for (int j = tid; j < HID; j += 128) ss[j] = g_sen_s[b * HID + j];
    __syncthreads();
    if (tid < NREL) {
        float a = sen_d[tid];
        const float *row = rel + (size_t)tid * HID;
        for (int j = 0; j < HID; j++) a += ss[j] * row[j];
        lg[tid] = a;
    }
    __syncthreads();
    if (tid == 0) {
        float mm = lg[0]; int am = 0;
        for (int c = 1; c < NREL; c++) if (lg[c] > mm) { mm = lg[c]; am = c; }
        mmax = mm; amax = am;
        float sum = 0.f;
        for (int c = 0; c < NREL; c++) sum += expf(lg[c] - mm);
        dsum = sum;
    }
    __syncthreads();
    if (tid < NREL) out[1 + NBAG + b * NREL + tid] = expf(lg[tid] - mmax) / dsum;
    if (tid == 0) {
        float loss = 0.f; int lab = 0;
        for (int c = 0; c < NREL; c++) {
            float l = lg[c], yv = y[b * NREL + c];
            loss += fmaxf(l, 0.f) - l * yv + log1pf(expf(-fabsf(l)));
            if (yv > 0.5f) lab = c;
        }
        g_loss_part[b] = loss / (float)NREL;
        out[1 + b] = (amax == lab) ? 1.f : 0.f;
    }
}

__global__ void loss_sum_kernel(float *__restrict__ out) {
    if (threadIdx.x == 0) {
        float s = 0.f;
        for (int b = 0; b < NBAG; b++) s += g_loss_part[b];
        out[0] = s;
    }
}

// ---------------- launch ----------------
extern "C" void kernel_launch(void *const *d_in, const int *in_sizes, int n_in,
                              void *d_out, int out_size) {
    const int *sentence = (const int *)d_in[0];
    const int *pos1 = (const int *)d_in[1];
    const int *pos2 = (const int *)d_in[2];
    const float *y_batch = (const float *)d_in[4];
    const float *word_emb = (const float *)d_in[5];
    const float *p1t = (const float *)d_in[6];
    const float *p2t = (const float *)d_in[7];
    const float *Wihf = (const float *)d_in[8];
    const float *Whhf = (const float *)d_in[9];
    const float *bihf = (const float *)d_in[10];
    const float *bhhf = (const float *)d_in[11];
    const float *Wihb = (const float *)d_in[12];
    const float *Whhb = (const float *)d_in[13];
    const float *bihb = (const float *)d_in[14];
    const float *bhhb = (const float *)d_in[15];
    const float *attw = (const float *)d_in[16];
    const float *sena = (const float *)d_in[17];
    const float *senr = (const float *)d_in[18];
    const float *rel = (const float *)d_in[19];
    const float *send = (const float *)d_in[20];
    float *out = (float *)d_out;

    cudaFuncSetAttribute(gru_step_kernel, cudaFuncAttributeMaxDynamicSharedMemorySize, SMEM_DYN);

    zero_kernel<<<(int)(((size_t)2 * 2 * 2 * 8 * N_TOT * 32 / 2 + 255) / 256), 256>>>();
    prep_w_kernel<<<(2 * 8 * 10 * 96 * 32 + 255) / 256, 256>>>(Wihf, Whhf, Wihb, Whhb);
    gather_kernel<<<(int)(((size_t)N_TOT * T_SEQ * 64 + 255) / 256), 256>>>(
        sentence, pos1, pos2, word_emb, p1t, p2t);

    dim3 grid(16, 8, 2);
    for (int s = 0; s < T_SEQ; s++) {
        gru_step_kernel<<<grid, NTHREADS, SMEM_DYN>>>(s, bihf, bhhf, bihb, bhhb);
    }

    attn_kernel<<<N_TOT, 256>>>(attw);
    bag_kernel<<<NBAG, 256>>>(sena, senr);
    logits_kernel<<<NBAG, 128>>>(rel, send, y_batch, out);
    loss_sum_kernel<<<1, 32>>>(out);
}

// round 10
// speedup vs baseline: 1.0343x; 1.0343x over previous
#include <cuda_runtime.h>
#include <cuda_bf16.h>
#include <math.h>
#include <stdint.h>

#define N_TOT 2048
#define T_SEQ 70
#define HID   230
#define DIN   60
#define EMB_W 50
#define NBAG  64
#define BAGSZ 32
#define NREL  100

// GRU step: M=128, N=192 (64j x 3 gates), K=320 (2 emb + 8 h chunks of 32)
// grid (16 Mtiles, 4 jtiles, 2 dirs) = 128 CTAs -> ONE wave at 1 CTA/SM.
// stage: A_hi[128*64B] A_lo | B_hi[192*64B] B_lo  = 40960 B, 3-stage ring.
#define NTHREADS 512
#define STAGE_B  40960
#define A_LO_OFF 8192
#define B_HI_OFF 16384
#define B_PART   12288
#define DUMP_OFF (3 * STAGE_B)             // 122880
#define SMEM_DYN (DUMP_OFF + 64 * 132 * 4) // 156672

// ---------------- device scratch (pre-swizzled, chunk-major) ----------------
__device__ __align__(128) __nv_bfloat16 g_Wt[(size_t)2 * 4 * 2 * 10 * 192 * 32]; // [dir][jt][part][chunk][12KB swz]
__device__ __align__(128) __nv_bfloat16 g_embsp[(size_t)T_SEQ * 2 * 2 * N_TOT * 32]; // [t][part][chunk2][n rows swz]
__device__ __align__(128) __nv_bfloat16 g_hbf[(size_t)2 * 2 * 2 * 8 * N_TOT * 32];   // [buf][dir][part][chunk8][n rows swz]
__device__ float g_hT[(size_t)2 * 2 * 256 * N_TOT];                               // [buf][dir][j][n]
__device__ float g_tup[(size_t)2 * T_SEQ * N_TOT * HID];                          // [dir][t][n][j]
__device__ float g_repre[N_TOT * HID];
__device__ float g_sen_s[NBAG * HID];
__device__ float g_loss_part[NBAG];

// ---------------- ptx helpers ----------------
__device__ __forceinline__ uint32_t smem_u32(const void *p) {
    uint32_t a;
    asm("{ .reg .u64 t; cvta.to.shared.u64 t, %1; cvt.u32.u64 %0, t; }" : "=r"(a) : "l"(p));
    return a;
}
#define BULK_G2S(dst, src, bytes, mbar)                                               \
    asm volatile(                                                                     \
        "cp.async.bulk.shared::cluster.global.mbarrier::complete_tx::bytes "          \
        "[%0], [%1], %2, [%3];"                                                       \
        :: "r"((uint32_t)(dst)), "l"(src), "r"((uint32_t)(bytes)),                    \
           "r"((uint32_t)(mbar)) : "memory")
#define MBARRIER_INIT(mb, cnt) \
    asm volatile("mbarrier.init.shared.b64 [%0], %1;" :: "r"((uint32_t)(mb)), "r"((uint32_t)(cnt)) : "memory")
#define MBARRIER_EXPECT_TX(mb, tx) \
    asm volatile("mbarrier.arrive.expect_tx.shared.b64 _, [%0], %1;" :: "r"((uint32_t)(mb)), "r"((uint32_t)(tx)) : "memory")
#define MBARRIER_ARRIVE(mb) \
    asm volatile("mbarrier.arrive.shared.b64 _, [%0];" :: "r"((uint32_t)(mb)) : "memory")
#define FENCE_ASYNC_SHARED() asm volatile("fence.proxy.async.shared::cta;" ::: "memory")
#define MBARRIER_WAIT_PARITY(mb, ph) do {                                             \
    uint32_t _m = (uint32_t)(mb); uint32_t _p = (uint32_t)(ph); uint32_t _d;          \
    asm volatile("{\n\t.reg .pred p;\n\t"                                             \
        "mbarrier.try_wait.parity.acquire.cta.shared::cta.b64 p, [%1], %2;\n\t"       \
        "selp.b32 %0, 1, 0, p;\n\t}" : "=r"(_d) : "r"(_m), "r"(_p) : "memory");       \
    if (!_d) {                                                                        \
        asm volatile("{\n\t.reg .pred P1;\n\t"                                        \
            "WL_%=:\n\t"                                                              \
            "mbarrier.try_wait.parity.acquire.cta.shared::cta.b64 P1, [%0], %1, 0x989680;\n\t" \
            "@P1 bra.uni WD_%=;\n\tbra.uni WL_%=;\n\tWD_%=:\n\t}"                     \
            :: "r"(_m), "r"(_p) : "memory");                                          \
    }                                                                                 \
} while (0)
#define LDSM4(r, a)                                                                   \
    asm volatile("ldmatrix.sync.aligned.m8n8.x4.shared.b16 {%0,%1,%2,%3}, [%4];"      \
                 : "=r"((r)[0]), "=r"((r)[1]), "=r"((r)[2]), "=r"((r)[3]) : "r"(a))
#define MMA16816(c, a, b0, b1)                                                        \
    asm volatile("mma.sync.aligned.m16n8k16.row.col.f32.bf16.bf16.f32 "               \
                 "{%0,%1,%2,%3},{%4,%5,%6,%7},{%8,%9},{%0,%1,%2,%3};"                 \
                 : "+f"((c)[0]), "+f"((c)[1]), "+f"((c)[2]), "+f"((c)[3])             \
                 : "r"((a)[0]), "r"((a)[1]), "r"((a)[2]), "r"((a)[3]), "r"(b0), "r"(b1))

__device__ __forceinline__ uint32_t pack2(__nv_bfloat16 a, __nv_bfloat16 b) {
    unsigned short ra = *(unsigned short *)&a, rb = *(unsigned short *)&b;
    return (uint32_t)ra | ((uint32_t)rb << 16);
}
// swizzled byte offset: 64B rows, 16B segs permuted within 8-row (512B) blocks
__device__ __forceinline__ uint32_t swz(int row, int seg) {
    return (uint32_t)row * 64u + (uint32_t)((seg ^ ((row >> 1) & 3)) << 4);
}
__device__ __forceinline__ uint32_t swz_elem(int row, int kc) {
    return (swz(row, kc >> 3) + (uint32_t)(kc & 7) * 2u) >> 1;
}

// ---------------- prep kernels ----------------
__global__ void zero_kernel() {
    size_t i = (size_t)blockIdx.x * blockDim.x + threadIdx.x;
    size_t nh = (size_t)2 * 2 * 2 * 8 * N_TOT * 32 / 2;
    if (i < nh) ((uint32_t *)g_hbf)[i] = 0u;
    if (i < (size_t)2 * 2 * 256 * N_TOT) g_hT[i] = 0.f;
}

// weights -> [dir][jt(4)][part][chunk(10)] contiguous 12288B swizzled; row = j_local*3+gate
__global__ void prep_w_kernel(const float *__restrict__ Wihf, const float *__restrict__ Whhf,
                              const float *__restrict__ Wihb, const float *__restrict__ Whhb) {
    int idx = blockIdx.x * blockDim.x + threadIdx.x;
    if (idx >= 2 * 4 * 10 * 192 * 32) return;
    int kc = idx & 31;
    int r = (idx >> 5) % 192;
    int rest = idx / (192 * 32);
    int c = rest % 10;
    int jt = (rest / 10) & 3;
    int dir = rest / 40;
    const float *Wih = dir ? Wihb : Wihf;
    const float *Whh = dir ? Whhb : Whhf;
    int j = jt * 64 + r / 3;
    int g = r % 3;
    float v = 0.f;
    if (j < HID) {
        if (c < 2) {
            int k = c * 32 + kc;
            if (k < DIN) v = Wih[(g * HID + j) * DIN + k];
        } else {
            int kh = (c - 2) * 32 + kc;
            if (kh < HID) v = Whh[(g * HID + j) * HID + kh];
        }
    }
    __nv_bfloat16 hi = __float2bfloat16(v);
    __nv_bfloat16 lo = __float2bfloat16(v - __bfloat162float(hi));
    uint32_t off = swz_elem(r, kc);
    size_t b0 = (((size_t)(dir * 4 + jt) * 2 + 0) * 10 + c) * (192 * 32);
    size_t b1 = (((size_t)(dir * 4 + jt) * 2 + 1) * 10 + c) * (192 * 32);
    g_Wt[b0 + off] = hi;
    g_Wt[b1 + off] = lo;
}

__global__ void gather_kernel(const int *__restrict__ sent, const int *__restrict__ p1,
                              const int *__restrict__ p2, const float *__restrict__ wemb,
                              const float *__restrict__ p1t, const float *__restrict__ p2t) {
    size_t idx = (size_t)blockIdx.x * blockDim.x + threadIdx.x;
    if (idx >= (size_t)N_TOT * T_SEQ * 64) return;
    int k = (int)(idx & 63);
    size_t nt = idx >> 6;
    int t = (int)(nt % T_SEQ);
    int n = (int)(nt / T_SEQ);
    float v = 0.f;
    if (k < EMB_W) v = wemb[(size_t)sent[n * T_SEQ + t] * EMB_W + k];
    else if (k < EMB_W + 5) v = p1t[p1[n * T_SEQ + t] * 5 + (k - EMB_W)];
    else if (k < DIN) v = p2t[p2[n * T_SEQ + t] * 5 + (k - EMB_W - 5)];
    __nv_bfloat16 hi = __float2bfloat16(v);
    __nv_bfloat16 lo = __float2bfloat16(v - __bfloat162float(hi));
    int chunk = k >> 5, kc = k & 31;
    uint32_t off = swz_elem(n, kc);
    size_t b0 = (((size_t)t * 2 + 0) * 2 + chunk) * (N_TOT * 32);
    size_t b1 = (((size_t)t * 2 + 1) * 2 + chunk) * (N_TOT * 32);
    g_embsp[b0 + off] = hi;
    g_embsp[b1 + off] = lo;
}

// ---------------- GRU step (bf16 3-pass, 16 warps, reg-pipelined) ----------
__global__ void __launch_bounds__(NTHREADS, 1) gru_step_kernel(
    int s,
    const float *__restrict__ bihf, const float *__restrict__ bhhf,
    const float *__restrict__ bihb, const float *__restrict__ bhhb) {
    extern __shared__ char dsm[];
    const int dir = blockIdx.z;
    const int t = dir ? (T_SEQ - 1 - s) : s;
    const int n0 = blockIdx.x * 128;
    const int jt = blockIdx.y;                  // 0..3 (64 j each)
    const int tid = threadIdx.x;
    const int lane = tid & 31, wid = tid >> 5;  // 16 warps
    const int warpM = wid & 3, warpN = wid >> 2;  // warpN 0..3 (48 cols each)
    const int bufi = s & 1, bufo = (s + 1) & 1;
    const float *bih = dir ? bihb : bihf;
    const float *bhh = dir ? bhhb : bhhf;

    const uint32_t base = smem_u32(dsm);
    float *dumpIN = (float *)(dsm + DUMP_OFF);  // [64][132]
    __shared__ float bs[4][64];
    __shared__ __align__(8) unsigned long long mbar[6];   // full[3], empty[3]
    const uint32_t mbF = smem_u32(mbar);
    const uint32_t mbE = mbF + 24;

    if (tid < 64) {
        int j = jt * 64 + tid;
        bool ok = j < HID;
        bs[0][tid] = ok ? (bih[j] + bhh[j]) : 0.f;
        bs[1][tid] = ok ? (bih[HID + j] + bhh[HID + j]) : 0.f;
        bs[2][tid] = ok ? bih[2 * HID + j] : 0.f;
        bs[3][tid] = ok ? bhh[2 * HID + j] : 0.f;
    }
    if (tid == 0) {
        MBARRIER_INIT(mbF, 1);
        MBARRIER_INIT(mbF + 8, 1);
        MBARRIER_INIT(mbF + 16, 1);
        MBARRIER_INIT(mbE, 16);
        MBARRIER_INIT(mbE + 8, 16);
        MBARRIER_INIT(mbE + 16, 16);
        FENCE_ASYNC_SHARED();
    }
    __syncthreads();

    const __nv_bfloat16 *embp = g_embsp + (size_t)t * 2 * 2 * N_TOT * 32 + (size_t)n0 * 32;
    const __nv_bfloat16 *hbfp = g_hbf + (size_t)((bufi * 2 + dir) * 2) * 8 * N_TOT * 32 + (size_t)n0 * 32;
    const __nv_bfloat16 *wbase = g_Wt + (size_t)(dir * 4 + jt) * 2 * 10 * (192 * 32);

    auto arm = [&](int k) {
        if (k >= 3) MBARRIER_WAIT_PARITY(mbE + (uint32_t)(k % 3) * 8, ((k / 3) + 1) & 1);
        uint32_t st = base + (uint32_t)(k % 3) * STAGE_B;
        uint32_t mb = mbF + (uint32_t)(k % 3) * 8;
        MBARRIER_EXPECT_TX(mb, STAGE_B);
#pragma unroll
        for (int part = 0; part < 2; part++) {
            const __nv_bfloat16 *Ap = (k < 2)
                ? embp + ((size_t)part * 2 + k) * (N_TOT * 32)
                : hbfp + ((size_t)part * 8 + (k - 2)) * (N_TOT * 32);
            BULK_G2S(st + part * A_LO_OFF, Ap, 8192, mb);
            const __nv_bfloat16 *Bp = wbase + ((size_t)part * 10 + k) * (192 * 32);
            BULK_G2S(st + B_HI_OFF + part * B_PART, Bp, B_PART, mb);
        }
    };

    if (tid == 0) { arm(0); arm(1); arm(2); }

    float acc[2][6][4];   // [mi][np*2+cp][frag]
#pragma unroll
    for (int mi = 0; mi < 2; mi++)
#pragma unroll
        for (int ni = 0; ni < 6; ni++)
#pragma unroll
            for (int q = 0; q < 4; q++) acc[mi][ni][q] = 0.f;

    const int laneR = lane & 15;
    const int laneHi = lane >> 4;
    const int gr = lane >> 2, lc = lane & 3;

    // A fragments double-buffered across stages; B loaded per stage
    uint32_t ah[2][2][4], al[2][2][4];

    auto ldsmA = [&](int buf, int c, int ks) {
        uint32_t sA = base + (uint32_t)(c % 3) * STAGE_B;
#pragma unroll
        for (int mi = 0; mi < 2; mi++) {
            int row = warpM * 32 + mi * 16 + laneR;
            uint32_t off = swz(row, ks * 2 + laneHi);
            LDSM4(ah[buf][mi], sA + off);
            LDSM4(al[buf][mi], sA + A_LO_OFF + off);
        }
    };

    MBARRIER_WAIT_PARITY(mbF, 0);
    ldsmA(0, 0, 0);
#pragma unroll
    for (int g = 0; g < 20; g++) {
        const int c = g >> 1, ks = g & 1;
        const int buf = g & 1;
        // B fragments for current stage
        uint32_t bh[3][4], bl[3][4];
        {
            uint32_t sB = base + (uint32_t)(c % 3) * STAGE_B + B_HI_OFF;
#pragma unroll
            for (int np = 0; np < 3; np++) {
                int row = warpN * 48 + np * 16 + laneR;
                uint32_t off = swz(row, ks * 2 + laneHi);
                LDSM4(bh[np], sB + off);
                LDSM4(bl[np], sB + B_PART + off);
            }
        }
        // prefetch next stage's A
        if (g < 19) {
            const int gn = g + 1, cn = gn >> 1, ksn = gn & 1;
            if (ksn == 0) MBARRIER_WAIT_PARITY(mbF + (uint32_t)(cn % 3) * 8, (cn / 3) & 1);
            ldsmA(buf ^ 1, cn, ksn);
        }
        // 36 MMAs, pass-major for RAW spacing
#pragma unroll
        for (int np = 0; np < 3; np++)
#pragma unroll
            for (int pass = 0; pass < 3; pass++) {
                const uint32_t(*aa)[4] = (pass == 2) ? al[buf] : ah[buf];
                const uint32_t *bb = (pass == 1) ? bl[np] : bh[np];
#pragma unroll
                for (int mi = 0; mi < 2; mi++) {
                    MMA16816(acc[mi][np * 2], aa[mi], bb[0], bb[2]);
                    MMA16816(acc[mi][np * 2 + 1], aa[mi], bb[1], bb[3]);
                }
            }
        if (ks == 1) {
            if (lane == 0) MBARRIER_ARRIVE(mbE + (uint32_t)(c % 3) * 8);
            if (tid == 0 && c + 3 < 10) arm(c + 3);
        }
        if (g == 3) {
            // emb phase done: move i_n slots (col%3==2) to dumpIN, zero them
#pragma unroll
            for (int mi = 0; mi < 2; mi++)
#pragma unroll
                for (int ni = 0; ni < 6; ni++)
#pragma unroll
                    for (int b = 0; b < 2; b++) {
                        int col = warpN * 48 + ni * 8 + lc * 2 + b;
                        if (col % 3 == 2) {
                            int jl = col / 3;
                            int m0 = warpM * 32 + mi * 16 + gr;
                            dumpIN[jl * 132 + m0] = acc[mi][ni][b];
                            dumpIN[jl * 132 + m0 + 8] = acc[mi][ni][b + 2];
                            acc[mi][ni][b] = 0.f;
                            acc[mi][ni][b + 2] = 0.f;
                        }
                    }
        }
    }

    __syncthreads();   // all warps done with stages; reuse for D staging
    float *D2 = (float *)dsm;   // [192 col][132]  (101 KB < 120 KB stage region)
#pragma unroll
    for (int mi = 0; mi < 2; mi++)
#pragma unroll
        for (int ni = 0; ni < 6; ni++) {
            int col0 = warpN * 48 + ni * 8 + lc * 2;
            int m0 = warpM * 32 + mi * 16 + gr;
            D2[col0 * 132 + m0] = acc[mi][ni][0];
            D2[(col0 + 1) * 132 + m0] = acc[mi][ni][1];
            D2[col0 * 132 + m0 + 8] = acc[mi][ni][2];
            D2[(col0 + 1) * 132 + m0 + 8] = acc[mi][ni][3];
        }
    __syncthreads();

    // gates: 512 work items (64 jl x 8 nsegs of 16)
    {
        int jl = tid >> 3, nseg = tid & 7;
        int j = jt * 64 + jl;
        int nb = nseg * 16;
        float br = bs[0][jl], bz = bs[1][jl], bin = bs[2][jl], bhn = bs[3][jl];
        const float4 *holdp = (const float4 *)(g_hT + ((size_t)(bufi * 2 + dir) * 256 + j) * N_TOT + n0 + nb);
        float4 *hnewp = (float4 *)(g_hT + ((size_t)(bufo * 2 + dir) * 256 + j) * N_TOT + n0 + nb);
        const float *Dr = D2 + (jl * 3 + 0) * 132 + nb;
        const float *Dz = D2 + (jl * 3 + 1) * 132 + nb;
        const float *Dn = D2 + (jl * 3 + 2) * 132 + nb;
        const float *Di = dumpIN + jl * 132 + nb;
        float hv[16];
#pragma unroll
        for (int v4 = 0; v4 < 4; v4++) {
            float4 hold4 = holdp[v4];
            float ho[4] = {hold4.x, hold4.y, hold4.z, hold4.w};
            float4 out4;
            float *o = (float *)&out4;
#pragma unroll
            for (int q = 0; q < 4; q++) {
                int i = v4 * 4 + q;
                float r = 1.f / (1.f + expf(-(Dr[i] + br)));
                float z = 1.f / (1.f + expf(-(Dz[i] + bz)));
                float nn = tanhf(Di[i] + bin + r * (Dn[i] + bhn));
                float h = (1.f - z) * nn + z * ho[q];
                hv[i] = h;
                o[q] = h;
            }
            hnewp[v4] = out4;
        }
#pragma unroll
        for (int i = 0; i < 16; i++) D2[(jl * 3) * 132 + nb + i] = hv[i];
    }
    __syncthreads();

    // writeout: tup fp32 [n][j]; h bf16 hi/lo chunk-major pre-swizzled; 1024 items
    {
        float *tupp = g_tup + (((size_t)dir * T_SEQ + t) * N_TOT) * HID;
#pragma unroll
        for (int it = 0; it < 2; it++) {
            int l = it * NTHREADS + tid;   // 0..1023
            int nl = l >> 3, seg8 = l & 7;
            int n = n0 + nl;
            int jb = seg8 * 8;             // 0..56 within 64-j tile
            float v[8];
#pragma unroll
            for (int q = 0; q < 8; q++) v[q] = D2[((jb + q) * 3) * 132 + nl];
#pragma unroll
            for (int q = 0; q < 8; q++) {
                int j = jt * 64 + jb + q;
                if (j < HID) tupp[(size_t)n * HID + j] = v[q];
            }
            __nv_bfloat16 hi[8], lo[8];
#pragma unroll
            for (int q = 0; q < 8; q++) {
                hi[q] = __float2bfloat16(v[q]);
                lo[q] = __float2bfloat16(v[q] - __bfloat162float(hi[q]));
            }
            uint4 vh, vl;
            vh.x = pack2(hi[0], hi[1]); vh.y = pack2(hi[2], hi[3]);
            vh.z = pack2(hi[4], hi[5]); vh.w = pack2(hi[6], hi[7]);
            vl.x = pack2(lo[0], lo[1]); vl.y = pack2(lo[2], lo[3]);
            vl.z = pack2(lo[4], lo[5]); vl.w = pack2(lo[6], lo[7]);
            int hch = jt * 2 + (seg8 >> 2);       // global h-chunk 0..7
            uint32_t off = swz(n, seg8 & 3);
            __nv_bfloat16 *hb0 = g_hbf + ((((size_t)(bufo * 2 + dir) * 2 + 0) * 8 + hch) * N_TOT) * 32;
            __nv_bfloat16 *hb1 = g_hbf + ((((size_t)(bufo * 2 + dir) * 2 + 1) * 8 + hch) * N_TOT) * 32;
            *(uint4 *)((char *)hb0 + off) = vh;
            *(uint4 *)((char *)hb1 + off) = vl;
        }
    }
}

// ---------------- word-level attention ----------------
__global__ void __launch_bounds__(256) attn_kernel(const float *__restrict__ att_w) {
    const int n = blockIdx.x;
    const int tid = threadIdx.x;
    __shared__ float xsum[HID];
    __shared__ float red[8];
    __shared__ float s_bc;
    float acc = 0.f, m = -1e30f, denom = 0.f;
    float w = (tid < HID) ? att_w[tid] : 0.f;
    for (int t = 0; t < T_SEQ; t++) {
        if (tid < HID) {
            size_t i0 = (((size_t)0 * T_SEQ + t) * N_TOT + n) * HID + tid;
            size_t i1 = (((size_t)1 * T_SEQ + t) * N_TOT + n) * HID + tid;
            xsum[tid] = g_tup[i0] + g_tup[i1];
        }
        __syncthreads();
        float part = (tid < HID) ? tanhf(xsum[tid]) * w : 0.f;
#pragma unroll
        for (int o = 16; o > 0; o >>= 1) part += __shfl_down_sync(0xffffffffu, part, o);
        if ((tid & 31) == 0) red[tid >> 5] = part;
        __syncthreads();
        if (tid == 0) {
            float sm = 0.f;
#pragma unroll
            for (int q = 0; q < 8; q++) sm += red[q];
            s_bc = sm;
        }
        __syncthreads();
        float st = s_bc;
        float mn = fmaxf(m, st);
        float cc = expf(m - mn), e = expf(st - mn);
        denom = denom * cc + e;
        if (tid < HID) acc = acc * cc + e * xsum[tid];
        m = mn;
        __syncthreads();
    }
    if (tid < HID) g_repre[n * HID + tid] = tanhf(acc / denom);
}

// ---------------- bag attention ----------------
__global__ void __launch_bounds__(256) bag_kernel(const float *__restrict__ sen_a,
                                                  const float *__restrict__ sen_r) {
    const int b = blockIdx.x;
    const int tid = threadIdx.x;
    __shared__ float R[BAGSZ][HID];
    __shared__ float sv[BAGSZ];
    __shared__ float alpha[BAGSZ];
    for (int l = tid; l < BAGSZ * HID; l += 256) {
        int i = l / HID, j = l % HID;
        R[i][j] = g_repre[(b * BAGSZ + i) * HID + j];
    }
    __syncthreads();
    int wid = tid >> 5, lane = tid & 31;
    for (int i = wid; i < BAGSZ; i += 8) {
        float p = 0.f;
        for (int j = lane; j < HID; j += 32) p += R[i][j] * sen_a[j] * sen_r[j];
#pragma unroll
        for (int o = 16; o > 0; o >>= 1) p += __shfl_down_sync(0xffffffffu, p, o);
        if (lane == 0) sv[i] = p;
    }
    __syncthreads();
    if (tid == 0) {
        float mm = -1e30f;
        for (int i = 0; i < BAGSZ; i++) mm = fmaxf(mm, sv[i]);
        float ss = 0.f;
        for (int i = 0; i < BAGSZ; i++) { float e = expf(sv[i] - mm); alpha[i] = e; ss += e; }
        for (int i = 0; i < BAGSZ; i++) alpha[i] /= ss;
    }
    __syncthreads();
    for (int j = tid; j < HID; j += 256) {
        float a = 0.f;
#pragma unroll 4
        for (int i = 0; i < BAGSZ; i++) a += alpha[i] * R[i][j];
        g_sen_s[b * HID + j] = a;
    }
}

// ---------------- logits / prob / bce / acc ----------------
__global__ void __launch_bounds__(128) logits_kernel(const float *__restrict__ rel,
                                                     const float *__restrict__ sen_d,
                                                     const float *__restrict__ y,
                                                     float *__restrict__ out) {
    const int b = blockIdx.x;
    const int tid = threadIdx.x;
    __shared__ float ss[HID];
    __shared__ float lg[NREL];
    __shared__ float mmax;
    __shared__ int amax;
    __shared__ float dsum;
    for (int j = tid; j < HID; j += 128) ss[j] = g_sen_s[b * HID + j];
    __syncthreads();
    if (tid < NREL) {
        float a = sen_d[tid];
        const float *row = rel + (size_t)tid * HID;
        for (int j = 0; j < HID; j++) a += ss[j] * row[j];
        lg[tid] = a;
    }
    __syncthreads();
    if (tid == 0) {
        float mm = lg[0]; int am = 0;
        for (int c = 1; c < NREL; c++) if (lg[c] > mm) { mm = lg[c]; am = c; }
        mmax = mm; amax = am;
        float sum = 0.f;
        for (int c = 0; c < NREL; c++) sum += expf(lg[c] - mm);
        dsum = sum;
    }
    __syncthreads();
    if (tid < NREL) out[1 + NBAG + b * NREL + tid] = expf(lg[tid] - mmax) / dsum;
    if (tid == 0) {
        float loss = 0.f; int lab = 0;
        for (int c = 0; c < NREL; c++) {
            float l = lg[c], yv = y[b * NREL + c];
            loss += fmaxf(l, 0.f) - l * yv + log1pf(expf(-fabsf(l)));
            if (yv > 0.5f) lab = c;
        }
        g_loss_part[b] = loss / (float)NREL;
        out[1 + b] = (amax == lab) ? 1.f : 0.f;
    }
}

__global__ void loss_sum_kernel(float *__restrict__ out) {
    if (threadIdx.x == 0) {
        float s = 0.f;
        for (int b = 0; b < NBAG; b++) s += g_loss_part[b];
        out[0] = s;
    }
}

// ---------------- launch ----------------
extern "C" void kernel_launch(void *const *d_in, const int *in_sizes, int n_in,
                              void *d_out, int out_size) {
    const int *sentence = (const int *)d_in[0];
    const int *pos1 = (const int *)d_in[1];
    const int *pos2 = (const int *)d_in[2];
    const float *y_batch = (const float *)d_in[4];
    const float *word_emb = (const float *)d_in[5];
    const float *p1t = (const float *)d_in[6];
    const float *p2t = (const float *)d_in[7];
    const float *Wihf = (const float *)d_in[8];
    const float *Whhf = (const float *)d_in[9];
    const float *bihf = (const float *)d_in[10];
    const float *bhhf = (const float *)d_in[11];
    const float *Wihb = (const float *)d_in[12];
    const float *Whhb = (const float *)d_in[13];
    const float *bihb = (const float *)d_in[14];
    const float *bhhb = (const float *)d_in[15];
    const float *attw = (const float *)d_in[16];
    const float *sena = (const float *)d_in[17];
    const float *senr = (const float *)d_in[18];
    const float *rel = (const float *)d_in[19];
    const float *send = (const float *)d_in[20];
    float *out = (float *)d_out;

    cudaFuncSetAttribute(gru_step_kernel, cudaFuncAttributeMaxDynamicSharedMemorySize, SMEM_DYN);

    zero_kernel<<<(int)(((size_t)2 * 2 * 2 * 8 * N_TOT * 32 / 2 + 255) / 256), 256>>>();
    prep_w_kernel<<<(2 * 4 * 10 * 192 * 32 + 255) / 256, 256>>>(Wihf, Whhf, Wihb, Whhb);
    gather_kernel<<<(int)(((size_t)N_TOT * T_SEQ * 64 + 255) / 256), 256>>>(
        sentence, pos1, pos2, word_emb, p1t, p2t);

    dim3 grid(16, 4, 2);
    for (int s = 0; s < T_SEQ; s++) {
        gru_step_kernel<<<grid, NTHREADS, SMEM_DYN>>>(s, bihf, bhhf, bihb, bhhb);
    }

    attn_kernel<<<N_TOT, 256>>>(attw);
    bag_kernel<<<NBAG, 256>>>(sena, senr);
    logits_kernel<<<NBAG, 128>>>(rel, send, y_batch, out);
    loss_sum_kernel<<<1, 32>>>(out);
}

// round 11
// speedup vs baseline: 1.0358x; 1.0015x over previous
#include <cuda_runtime.h>
#include <cuda_bf16.h>
#include <math.h>
#include <stdint.h>

#define N_TOT 2048
#define T_SEQ 70
#define HID   230
#define DIN   60
#define EMB_W 50
#define NBAG  64
#define BAGSZ 32
#define NREL  100

// GRU step: M=128, N=192 (64j x 3 gates), K=320 (2 emb + 8 h chunks of 32)
// grid (16 Mtiles, 4 jtiles, 2 dirs) = 128 CTAs -> ONE wave at 1 CTA/SM.
// stage: A_hi[128*64B] A_lo | B_hi[192*64B] B_lo  = 40960 B, 3-stage ring.
#define NTHREADS 512
#define STAGE_B  40960
#define A_LO_OFF 8192
#define B_HI_OFF 16384
#define B_PART   12288
#define DUMP_OFF (3 * STAGE_B)             // 122880
#define SMEM_DYN (DUMP_OFF + 64 * 132 * 4) // 156672

// ---------------- device scratch (pre-swizzled, chunk-major) ----------------
__device__ __align__(128) __nv_bfloat16 g_Wt[(size_t)2 * 4 * 2 * 10 * 192 * 32]; // [dir][jt][part][chunk][12KB swz]
__device__ __align__(128) __nv_bfloat16 g_embsp[(size_t)T_SEQ * 2 * 2 * N_TOT * 32]; // [t][part][chunk2][n rows swz]
__device__ __align__(128) __nv_bfloat16 g_hbf[(size_t)2 * 2 * 2 * 8 * N_TOT * 32];   // [buf][dir][part][chunk8][n rows swz]
__device__ float g_hT[(size_t)2 * 2 * 256 * N_TOT];                               // [buf][dir][j][n]
__device__ float g_tup[(size_t)2 * T_SEQ * N_TOT * HID];                          // [dir][t][n][j]
__device__ float g_repre[N_TOT * HID];
__device__ float g_sen_s[NBAG * HID];
__device__ float g_loss_part[NBAG];

// ---------------- ptx helpers ----------------
__device__ __forceinline__ uint32_t smem_u32(const void *p) {
    uint32_t a;
    asm("{ .reg .u64 t; cvta.to.shared.u64 t, %1; cvt.u32.u64 %0, t; }" : "=r"(a) : "l"(p));
    return a;
}
#define BULK_G2S(dst, src, bytes, mbar)                                               \
    asm volatile(                                                                     \
        "cp.async.bulk.shared::cluster.global.mbarrier::complete_tx::bytes "          \
        "[%0], [%1], %2, [%3];"                                                       \
        :: "r"((uint32_t)(dst)), "l"(src), "r"((uint32_t)(bytes)),                    \
           "r"((uint32_t)(mbar)) : "memory")
#define MBARRIER_INIT(mb, cnt) \
    asm volatile("mbarrier.init.shared.b64 [%0], %1;" :: "r"((uint32_t)(mb)), "r"((uint32_t)(cnt)) : "memory")
#define MBARRIER_EXPECT_TX(mb, tx) \
    asm volatile("mbarrier.arrive.expect_tx.shared.b64 _, [%0], %1;" :: "r"((uint32_t)(mb)), "r"((uint32_t)(tx)) : "memory")
#define MBARRIER_ARRIVE(mb) \
    asm volatile("mbarrier.arrive.shared.b64 _, [%0];" :: "r"((uint32_t)(mb)) : "memory")
#define FENCE_ASYNC_SHARED() asm volatile("fence.proxy.async.shared::cta;" ::: "memory")
#define MBARRIER_WAIT_PARITY(mb, ph) do {                                             \
    uint32_t _m = (uint32_t)(mb); uint32_t _p = (uint32_t)(ph); uint32_t _d;          \
    asm volatile("{\n\t.reg .pred p;\n\t"                                             \
        "mbarrier.try_wait.parity.acquire.cta.shared::cta.b64 p, [%1], %2;\n\t"       \
        "selp.b32 %0, 1, 0, p;\n\t}" : "=r"(_d) : "r"(_m), "r"(_p) : "memory");       \
    if (!_d) {                                                                        \
        asm volatile("{\n\t.reg .pred P1;\n\t"                                        \
            "WL_%=:\n\t"                                                              \
            "mbarrier.try_wait.parity.acquire.cta.shared::cta.b64 P1, [%0], %1, 0x989680;\n\t" \
            "@P1 bra.uni WD_%=;\n\tbra.uni WL_%=;\n\tWD_%=:\n\t}"                     \
            :: "r"(_m), "r"(_p) : "memory");                                          \
    }                                                                                 \
} while (0)
#define LDSM4(r, a)                                                                   \
    asm volatile("ldmatrix.sync.aligned.m8n8.x4.shared.b16 {%0,%1,%2,%3}, [%4];"      \
                 : "=r"((r)[0]), "=r"((r)[1]), "=r"((r)[2]), "=r"((r)[3]) : "r"(a))
#define MMA16816(c, a, b0, b1)                                                        \
    asm volatile("mma.sync.aligned.m16n8k16.row.col.f32.bf16.bf16.f32 "               \
                 "{%0,%1,%2,%3},{%4,%5,%6,%7},{%8,%9},{%0,%1,%2,%3};"                 \
                 : "+f"((c)[0]), "+f"((c)[1]), "+f"((c)[2]), "+f"((c)[3])             \
                 : "r"((a)[0]), "r"((a)[1]), "r"((a)[2]), "r"((a)[3]), "r"(b0), "r"(b1))

__device__ __forceinline__ uint32_t pack2(__nv_bfloat16 a, __nv_bfloat16 b) {
    unsigned short ra = *(unsigned short *)&a, rb = *(unsigned short *)&b;
    return (uint32_t)ra | ((uint32_t)rb << 16);
}
// swizzled byte offset: 64B rows, 16B segs permuted within 8-row (512B) blocks
__device__ __forceinline__ uint32_t swz(int row, int seg) {
    return (uint32_t)row * 64u + (uint32_t)((seg ^ ((row >> 1) & 3)) << 4);
}
__device__ __forceinline__ uint32_t swz_elem(int row, int kc) {
    return (swz(row, kc >> 3) + (uint32_t)(kc & 7) * 2u) >> 1;
}

// ---------------- prep kernels ----------------
__global__ void zero_kernel() {
    size_t i = (size_t)blockIdx.x * blockDim.x + threadIdx.x;
    size_t nh = (size_t)2 * 2 * 2 * 8 * N_TOT * 32 / 2;
    if (i < nh) ((uint32_t *)g_hbf)[i] = 0u;
    if (i < (size_t)2 * 2 * 256 * N_TOT) g_hT[i] = 0.f;
}

// weights -> [dir][jt(4)][part][chunk(10)] contiguous 12288B swizzled; row = j_local*3+gate
__global__ void prep_w_kernel(const float *__restrict__ Wihf, const float *__restrict__ Whhf,
                              const float *__restrict__ Wihb, const float *__restrict__ Whhb) {
    int idx = blockIdx.x * blockDim.x + threadIdx.x;
    if (idx >= 2 * 4 * 10 * 192 * 32) return;
    int kc = idx & 31;
    int r = (idx >> 5) % 192;
    int rest = idx / (192 * 32);
    int c = rest % 10;
    int jt = (rest / 10) & 3;
    int dir = rest / 40;
    const float *Wih = dir ? Wihb : Wihf;
    const float *Whh = dir ? Whhb : Whhf;
    int j = jt * 64 + r / 3;
    int g = r % 3;
    float v = 0.f;
    if (j < HID) {
        if (c < 2) {
            int k = c * 32 + kc;
            if (k < DIN) v = Wih[(g * HID + j) * DIN + k];
        } else {
            int kh = (c - 2) * 32 + kc;
            if (kh < HID) v = Whh[(g * HID + j) * HID + kh];
        }
    }
    __nv_bfloat16 hi = __float2bfloat16(v);
    __nv_bfloat16 lo = __float2bfloat16(v - __bfloat162float(hi));
    uint32_t off = swz_elem(r, kc);
    size_t b0 = (((size_t)(dir * 4 + jt) * 2 + 0) * 10 + c) * (192 * 32);
    size_t b1 = (((size_t)(dir * 4 + jt) * 2 + 1) * 10 + c) * (192 * 32);
    g_Wt[b0 + off] = hi;
    g_Wt[b1 + off] = lo;
}

__global__ void gather_kernel(const int *__restrict__ sent, const int *__restrict__ p1,
                              const int *__restrict__ p2, const float *__restrict__ wemb,
                              const float *__restrict__ p1t, const float *__restrict__ p2t) {
    size_t idx = (size_t)blockIdx.x * blockDim.x + threadIdx.x;
    if (idx >= (size_t)N_TOT * T_SEQ * 64) return;
    int k = (int)(idx & 63);
    size_t nt = idx >> 6;
    int t = (int)(nt % T_SEQ);
    int n = (int)(nt / T_SEQ);
    float v = 0.f;
    if (k < EMB_W) v = wemb[(size_t)sent[n * T_SEQ + t] * EMB_W + k];
    else if (k < EMB_W + 5) v = p1t[p1[n * T_SEQ + t] * 5 + (k - EMB_W)];
    else if (k < DIN) v = p2t[p2[n * T_SEQ + t] * 5 + (k - EMB_W - 5)];
    __nv_bfloat16 hi = __float2bfloat16(v);
    __nv_bfloat16 lo = __float2bfloat16(v - __bfloat162float(hi));
    int chunk = k >> 5, kc = k & 31;
    uint32_t off = swz_elem(n, kc);
    size_t b0 = (((size_t)t * 2 + 0) * 2 + chunk) * (N_TOT * 32);
    size_t b1 = (((size_t)t * 2 + 1) * 2 + chunk) * (N_TOT * 32);
    g_embsp[b0 + off] = hi;
    g_embsp[b1 + off] = lo;
}

// ---------------- GRU step (bf16 3-pass, 16 warps, RAW-spaced MMA order) ----
__global__ void __launch_bounds__(NTHREADS, 1) gru_step_kernel(
    int s,
    const float *__restrict__ bihf, const float *__restrict__ bhhf,
    const float *__restrict__ bihb, const float *__restrict__ bhhb) {
    extern __shared__ char dsm[];
    const int dir = blockIdx.z;
    const int t = dir ? (T_SEQ - 1 - s) : s;
    const int n0 = blockIdx.x * 128;
    const int jt = blockIdx.y;                  // 0..3 (64 j each)
    const int tid = threadIdx.x;
    const int lane = tid & 31, wid = tid >> 5;  // 16 warps
    const int warpM = wid & 3, warpN = wid >> 2;  // warpN 0..3 (48 cols each)
    const int bufi = s & 1, bufo = (s + 1) & 1;
    const float *bih = dir ? bihb : bihf;
    const float *bhh = dir ? bhhb : bhhf;

    const uint32_t base = smem_u32(dsm);
    float *dumpIN = (float *)(dsm + DUMP_OFF);  // [64][132]
    __shared__ float bs[4][64];
    __shared__ __align__(8) unsigned long long mbar[6];   // full[3], empty[3]
    const uint32_t mbF = smem_u32(mbar);
    const uint32_t mbE = mbF + 24;

    if (tid < 64) {
        int j = jt * 64 + tid;
        bool ok = j < HID;
        bs[0][tid] = ok ? (bih[j] + bhh[j]) : 0.f;
        bs[1][tid] = ok ? (bih[HID + j] + bhh[HID + j]) : 0.f;
        bs[2][tid] = ok ? bih[2 * HID + j] : 0.f;
        bs[3][tid] = ok ? bhh[2 * HID + j] : 0.f;
    }
    if (tid == 0) {
        MBARRIER_INIT(mbF, 1);
        MBARRIER_INIT(mbF + 8, 1);
        MBARRIER_INIT(mbF + 16, 1);
        MBARRIER_INIT(mbE, 16);
        MBARRIER_INIT(mbE + 8, 16);
        MBARRIER_INIT(mbE + 16, 16);
        FENCE_ASYNC_SHARED();
    }
    __syncthreads();

    const __nv_bfloat16 *embp = g_embsp + (size_t)t * 2 * 2 * N_TOT * 32 + (size_t)n0 * 32;
    const __nv_bfloat16 *hbfp = g_hbf + (size_t)((bufi * 2 + dir) * 2) * 8 * N_TOT * 32 + (size_t)n0 * 32;
    const __nv_bfloat16 *wbase = g_Wt + (size_t)(dir * 4 + jt) * 2 * 10 * (192 * 32);

    auto arm = [&](int k) {
        if (k >= 3) MBARRIER_WAIT_PARITY(mbE + (uint32_t)(k % 3) * 8, ((k / 3) + 1) & 1);
        uint32_t st = base + (uint32_t)(k % 3) * STAGE_B;
        uint32_t mb = mbF + (uint32_t)(k % 3) * 8;
        MBARRIER_EXPECT_TX(mb, STAGE_B);
#pragma unroll
        for (int part = 0; part < 2; part++) {
            const __nv_bfloat16 *Ap = (k < 2)
                ? embp + ((size_t)part * 2 + k) * (N_TOT * 32)
                : hbfp + ((size_t)part * 8 + (k - 2)) * (N_TOT * 32);
            BULK_G2S(st + part * A_LO_OFF, Ap, 8192, mb);
            const __nv_bfloat16 *Bp = wbase + ((size_t)part * 10 + k) * (192 * 32);
            BULK_G2S(st + B_HI_OFF + part * B_PART, Bp, B_PART, mb);
        }
    };

    if (tid == 0) { arm(0); arm(1); arm(2); }

    float acc[2][6][4];   // [mi][np*2+cp][frag]
#pragma unroll
    for (int mi = 0; mi < 2; mi++)
#pragma unroll
        for (int ni = 0; ni < 6; ni++)
#pragma unroll
            for (int q = 0; q < 4; q++) acc[mi][ni][q] = 0.f;

    const int laneR = lane & 15;
    const int laneHi = lane >> 4;
    const int gr = lane >> 2, lc = lane & 3;

    // A fragments double-buffered across stages; B loaded per stage
    uint32_t ah[2][2][4], al[2][2][4];

    auto ldsmA = [&](int buf, int c, int ks) {
        uint32_t sA = base + (uint32_t)(c % 3) * STAGE_B;
#pragma unroll
        for (int mi = 0; mi < 2; mi++) {
            int row = warpM * 32 + mi * 16 + laneR;
            uint32_t off = swz(row, ks * 2 + laneHi);
            LDSM4(ah[buf][mi], sA + off);
            LDSM4(al[buf][mi], sA + A_LO_OFF + off);
        }
    };

    MBARRIER_WAIT_PARITY(mbF, 0);
    ldsmA(0, 0, 0);
#pragma unroll
    for (int g = 0; g < 20; g++) {
        const int c = g >> 1, ks = g & 1;
        const int buf = g & 1;
        // all LDSMs up front: B (current stage) ...
        uint32_t bh[3][4], bl[3][4];
        {
            uint32_t sB = base + (uint32_t)(c % 3) * STAGE_B + B_HI_OFF;
#pragma unroll
            for (int np = 0; np < 3; np++) {
                int row = warpN * 48 + np * 16 + laneR;
                uint32_t off = swz(row, ks * 2 + laneHi);
                LDSM4(bh[np], sB + off);
                LDSM4(bl[np], sB + B_PART + off);
            }
        }
        // ... then A prefetch for next stage
        if (g < 19) {
            const int gn = g + 1, cn = gn >> 1, ksn = gn & 1;
            if (ksn == 0) MBARRIER_WAIT_PARITY(mbF + (uint32_t)(cn % 3) * 8, (cn / 3) & 1);
            ldsmA(buf ^ 1, cn, ksn);
        }
        // 36 MMAs, PASS-OUTER / NP-MIDDLE: same-acc spacing = 12 MMAs (~77 cyc)
#pragma unroll
        for (int pass = 0; pass < 3; pass++) {
            const uint32_t(*aa)[4] = (pass == 2) ? al[buf] : ah[buf];
#pragma unroll
            for (int np = 0; np < 3; np++) {
                const uint32_t *bb = (pass == 1) ? bl[np] : bh[np];
#pragma unroll
                for (int mi = 0; mi < 2; mi++) {
                    MMA16816(acc[mi][np * 2], aa[mi], bb[0], bb[2]);
                    MMA16816(acc[mi][np * 2 + 1], aa[mi], bb[1], bb[3]);
                }
            }
        }
        if (ks == 1) {
            if (lane == 0) MBARRIER_ARRIVE(mbE + (uint32_t)(c % 3) * 8);
            if (tid == 0 && c + 3 < 10) arm(c + 3);
        }
        if (g == 3) {
            // emb phase done: move i_n slots (col%3==2) to dumpIN, zero them
#pragma unroll
            for (int mi = 0; mi < 2; mi++)
#pragma unroll
                for (int ni = 0; ni < 6; ni++)
#pragma unroll
                    for (int b = 0; b < 2; b++) {
                        int col = warpN * 48 + ni * 8 + lc * 2 + b;
                        if (col % 3 == 2) {
                            int jl = col / 3;
                            int m0 = warpM * 32 + mi * 16 + gr;
                            dumpIN[jl * 132 + m0] = acc[mi][ni][b];
                            dumpIN[jl * 132 + m0 + 8] = acc[mi][ni][b + 2];
                            acc[mi][ni][b] = 0.f;
                            acc[mi][ni][b + 2] = 0.f;
                        }
                    }
        }
    }

    __syncthreads();   // all warps done with stages; reuse for D staging
    float *D2 = (float *)dsm;   // [192 col][132]
#pragma unroll
    for (int mi = 0; mi < 2; mi++)
#pragma unroll
        for (int ni = 0; ni < 6; ni++) {
            int col0 = warpN * 48 + ni * 8 + lc * 2;
            int m0 = warpM * 32 + mi * 16 + gr;
            D2[col0 * 132 + m0] = acc[mi][ni][0];
            D2[(col0 + 1) * 132 + m0] = acc[mi][ni][1];
            D2[col0 * 132 + m0 + 8] = acc[mi][ni][2];
            D2[(col0 + 1) * 132 + m0 + 8] = acc[mi][ni][3];
        }
    __syncthreads();

    // gates: 512 work items (64 jl x 8 nsegs of 16)
    {
        int jl = tid >> 3, nseg = tid & 7;
        int j = jt * 64 + jl;
        int nb = nseg * 16;
        float br = bs[0][jl], bz = bs[1][jl], bin = bs[2][jl], bhn = bs[3][jl];
        const float4 *holdp = (const float4 *)(g_hT + ((size_t)(bufi * 2 + dir) * 256 + j) * N_TOT + n0 + nb);
        float4 *hnewp = (float4 *)(g_hT + ((size_t)(bufo * 2 + dir) * 256 + j) * N_TOT + n0 + nb);
        const float *Dr = D2 + (jl * 3 + 0) * 132 + nb;
        const float *Dz = D2 + (jl * 3 + 1) * 132 + nb;
        const float *Dn = D2 + (jl * 3 + 2) * 132 + nb;
        const float *Di = dumpIN + jl * 132 + nb;
        float hv[16];
#pragma unroll
        for (int v4 = 0; v4 < 4; v4++) {
            float4 hold4 = holdp[v4];
            float ho[4] = {hold4.x, hold4.y, hold4.z, hold4.w};
            float4 out4;
            float *o = (float *)&out4;
#pragma unroll
            for (int q = 0; q < 4; q++) {
                int i = v4 * 4 + q;
                float r = 1.f / (1.f + expf(-(Dr[i] + br)));
                float z = 1.f / (1.f + expf(-(Dz[i] + bz)));
                float nn = tanhf(Di[i] + bin + r * (Dn[i] + bhn));
                float h = (1.f - z) * nn + z * ho[q];
                hv[i] = h;
                o[q] = h;
            }
            hnewp[v4] = out4;
        }
#pragma unroll
        for (int i = 0; i < 16; i++) D2[(jl * 3) * 132 + nb + i] = hv[i];
    }
    __syncthreads();

    // writeout: tup fp32 [n][j]; h bf16 hi/lo chunk-major pre-swizzled; 1024 items
    {
        float *tupp = g_tup + (((size_t)dir * T_SEQ + t) * N_TOT) * HID;
#pragma unroll
        for (int it = 0; it < 2; it++) {
            int l = it * NTHREADS + tid;   // 0..1023
            int nl = l >> 3, seg8 = l & 7;
            int n = n0 + nl;
            int jb = seg8 * 8;             // 0..56 within 64-j tile
            float v[8];
#pragma unroll
            for (int q = 0; q < 8; q++) v[q] = D2[((jb + q) * 3) * 132 + nl];
#pragma unroll
            for (int q = 0; q < 8; q++) {
                int j = jt * 64 + jb + q;
                if (j < HID) tupp[(size_t)n * HID + j] = v[q];
            }
            __nv_bfloat16 hi[8], lo[8];
#pragma unroll
            for (int q = 0; q < 8; q++) {
                hi[q] = __float2bfloat16(v[q]);
                lo[q] = __float2bfloat16(v[q] - __bfloat162float(hi[q]));
            }
            uint4 vh, vl;
            vh.x = pack2(hi[0], hi[1]); vh.y = pack2(hi[2], hi[3]);
            vh.z = pack2(hi[4], hi[5]); vh.w = pack2(hi[6], hi[7]);
            vl.x = pack2(lo[0], lo[1]); vl.y = pack2(lo[2], lo[3]);
            vl.z = pack2(lo[4], lo[5]); vl.w = pack2(lo[6], lo[7]);
            int hch = jt * 2 + (seg8 >> 2);       // global h-chunk 0..7
            uint32_t off = swz(n, seg8 & 3);
            __nv_bfloat16 *hb0 = g_hbf + ((((size_t)(bufo * 2 + dir) * 2 + 0) * 8 + hch) * N_TOT) * 32;
            __nv_bfloat16 *hb1 = g_hbf + ((((size_t)(bufo * 2 + dir) * 2 + 1) * 8 + hch) * N_TOT) * 32;
            *(uint4 *)((char *)hb0 + off) = vh;
            *(uint4 *)((char *)hb1 + off) = vl;
        }
    }
}

// ---------------- word-level attention ----------------
__global__ void __launch_bounds__(256) attn_kernel(const float *__restrict__ att_w) {
    const int n = blockIdx.x;
    const int tid = threadIdx.x;
    __shared__ float xsum[HID];
    __shared__ float red[8];
    __shared__ float s_bc;
    float acc = 0.f, m = -1e30f, denom = 0.f;
    float w = (tid < HID) ? att_w[tid] : 0.f;
    for (int t = 0; t < T_SEQ; t++) {
        if (tid < HID) {
            size_t i0 = (((size_t)0 * T_SEQ + t) * N_TOT + n) * HID + tid;
            size_t i1 = (((size_t)1 * T_SEQ + t) * N_TOT + n) * HID + tid;
            xsum[tid] = g_tup[i0] + g_tup[i1];
        }
        __syncthreads();
        float part = (tid < HID) ? tanhf(xsum[tid]) * w : 0.f;
#pragma unroll
        for (int o = 16; o > 0; o >>= 1) part += __shfl_down_sync(0xffffffffu, part, o);
        if ((tid & 31) == 0) red[tid >> 5] = part;
        __syncthreads();
        if (tid == 0) {
            float sm = 0.f;
#pragma unroll
            for (int q = 0; q < 8; q++) sm += red[q];
            s_bc = sm;
        }
        __syncthreads();
        float st = s_bc;
        float mn = fmaxf(m, st);
        float cc = expf(m - mn), e = expf(st - mn);
        denom = denom * cc + e;
        if (tid < HID) acc = acc * cc + e * xsum[tid];
        m = mn;
        __syncthreads();
    }
    if (tid < HID) g_repre[n * HID + tid] = tanhf(acc / denom);
}

// ---------------- bag attention ----------------
__global__ void __launch_bounds__(256) bag_kernel(const float *__restrict__ sen_a,
                                                  const float *__restrict__ sen_r) {
    const int b = blockIdx.x;
    const int tid = threadIdx.x;
    __shared__ float R[BAGSZ][HID];
    __shared__ float sv[BAGSZ];
    __shared__ float alpha[BAGSZ];
    for (int l = tid; l < BAGSZ * HID; l += 256) {
        int i = l / HID, j = l % HID;
        R[i][j] = g_repre[(b * BAGSZ + i) * HID + j];
    }
    __syncthreads();
    int wid = tid >> 5, lane = tid & 31;
    for (int i = wid; i < BAGSZ; i += 8) {
        float p = 0.f;
        for (int j = lane; j < HID; j += 32) p += R[i][j] * sen_a[j] * sen_r[j];
#pragma unroll
        for (int o = 16; o > 0; o >>= 1) p += __shfl_down_sync(0xffffffffu, p, o);
        if (lane == 0) sv[i] = p;
    }
    __syncthreads();
    if (tid == 0) {
        float mm = -1e30f;
        for (int i = 0; i < BAGSZ; i++) mm = fmaxf(mm, sv[i]);
        float ss = 0.f;
        for (int i = 0; i < BAGSZ; i++) { float e = expf(sv[i] - mm); alpha[i] = e; ss += e; }
        for (int i = 0; i < BAGSZ; i++) alpha[i] /= ss;
    }
    __syncthreads();
    for (int j = tid; j < HID; j += 256) {
        float a = 0.f;
#pragma unroll 4
        for (int i = 0; i < BAGSZ; i++) a += alpha[i] * R[i][j];
        g_sen_s[b * HID + j] = a;
    }
}

// ---------------- logits / prob / bce / acc ----------------
__global__ void __launch_bounds__(128) logits_kernel(const float *__restrict__ rel,
                                                     const float *__restrict__ sen_d,
                                                     const float *__restrict__ y,
                                                     float *__restrict__ out) {
    const int b = blockIdx.x;
    const int tid = threadIdx.x;
    __shared__ float ss[HID];
    __shared__ float lg[NREL];
    __shared__ float mmax;
    __shared__ int amax;
    __shared__ float dsum;
    for (int j = tid; j < HID; j += 128) ss[j] = g_sen_s[b * HID + j];
    __syncthreads();
    if (tid < NREL) {
        float a = sen_d[tid];
        const float *row = rel + (size_t)tid * HID;
        for (int j = 0; j < HID; j++) a += ss[j] * row[j];
        lg[tid] = a;
    }
    __syncthreads();
    if (tid == 0) {
        float mm = lg[0]; int am = 0;
        for (int c = 1; c < NREL; c++) if (lg[c] > mm) { mm = lg[c]; am = c; }
        mmax = mm; amax = am;
        float sum = 0.f;
        for (int c = 0; c < NREL; c++) sum += expf(lg[c] - mm);
        dsum = sum;
    }
    __syncthreads();
    if (tid < NREL) out[1 + NBAG + b * NREL + tid] = expf(lg[tid] - mmax) / dsum;
    if (tid == 0) {
        float loss = 0.f; int lab = 0;
        for (int c = 0; c < NREL; c++) {
            float l = lg[c], yv = y[b * NREL + c];
            loss += fmaxf(l, 0.f) - l * yv + log1pf(expf(-fabsf(l)));
            if (yv > 0.5f) lab = c;
        }
        g_loss_part[b] = loss / (float)NREL;
        out[1 + b] = (amax == lab) ? 1.f : 0.f;
    }
}

__global__ void loss_sum_kernel(float *__restrict__ out) {
    if (threadIdx.x == 0) {
        float s = 0.f;
        for (int b = 0; b < NBAG; b++) s += g_loss_part[b];
        out[0] = s;
    }
}

// ---------------- launch ----------------
extern "C" void kernel_launch(void *const *d_in, const int *in_sizes, int n_in,
                              void *d_out, int out_size) {
    const int *sentence = (const int *)d_in[0];
    const int *pos1 = (const int *)d_in[1];
    const int *pos2 = (const int *)d_in[2];
    const float *y_batch = (const float *)d_in[4];
    const float *word_emb = (const float *)d_in[5];
    const float *p1t = (const float *)d_in[6];
    const float *p2t = (const float *)d_in[7];
    const float *Wihf = (const float *)d_in[8];
    const float *Whhf = (const float *)d_in[9];
    const float *bihf = (const float *)d_in[10];
    const float *bhhf = (const float *)d_in[11];
    const float *Wihb = (const float *)d_in[12];
    const float *Whhb = (const float *)d_in[13];
    const float *bihb = (const float *)d_in[14];
    const float *bhhb = (const float *)d_in[15];
    const float *attw = (const float *)d_in[16];
    const float *sena = (const float *)d_in[17];
    const float *senr = (const float *)d_in[18];
    const float *rel = (const float *)d_in[19];
    const float *send = (const float *)d_in[20];
    float *out = (float *)d_out;

    cudaFuncSetAttribute(gru_step_kernel, cudaFuncAttributeMaxDynamicSharedMemorySize, SMEM_DYN);

    zero_kernel<<<(int)(((size_t)2 * 2 * 2 * 8 * N_TOT * 32 / 2 + 255) / 256), 256>>>();
    prep_w_kernel<<<(2 * 4 * 10 * 192 * 32 + 255) / 256, 256>>>(Wihf, Whhf, Wihb, Whhb);
    gather_kernel<<<(int)(((size_t)N_TOT * T_SEQ * 64 + 255) / 256), 256>>>(
        sentence, pos1, pos2, word_emb, p1t, p2t);

    dim3 grid(16, 4, 2);
    for (int s = 0; s < T_SEQ; s++) {
        gru_step_kernel<<<grid, NTHREADS, SMEM_DYN>>>(s, bihf, bhhf, bihb, bhhb);
    }

    attn_kernel<<<N_TOT, 256>>>(attw);
    bag_kernel<<<NBAG, 256>>>(sena, senr);
    logits_kernel<<<NBAG, 128>>>(rel, send, y_batch, out);
    loss_sum_kernel<<<1, 32>>>(out);
}

// round 12
// speedup vs baseline: 1.0400x; 1.0040x over previous
#include <cuda_runtime.h>
#include <cuda_bf16.h>
#include <math.h>
#include <stdint.h>

#define N_TOT 2048
#define T_SEQ 70
#define HID   230
#define DIN   60
#define EMB_W 50
#define NBAG  64
#define BAGSZ 32
#define NREL  100

// GRU: persistent kernel, 128 CTAs (1/SM, single wave), 70 steps in-kernel.
// Per CTA: M=128, N=192 (64j x 3 gates), K=320 in 10 chunks of 32.
// stage: A_hi[8K] A_lo[8K] | B_hi[12K] B_lo[12K] = 40960 B, 3-slot TMA ring.
#define NTHREADS 512
#define STAGE_B  40960
#define A_LO_OFF 8192
#define B_HI_OFF 16384
#define B_PART   12288
#define DUMP_OFF (3 * STAGE_B)             // 122880
#define SMEM_DYN (DUMP_OFF + 64 * 132 * 4) // 156672

// ---------------- device scratch (pre-swizzled, chunk-major) ----------------
__device__ __align__(128) __nv_bfloat16 g_Wt[(size_t)2 * 4 * 2 * 10 * 192 * 32];
__device__ __align__(128) __nv_bfloat16 g_embsp[(size_t)T_SEQ * 2 * 2 * N_TOT * 32];
__device__ __align__(128) __nv_bfloat16 g_hbf[(size_t)2 * 2 * 2 * 8 * N_TOT * 32];
__device__ float g_hT[(size_t)2 * 2 * 256 * N_TOT];
__device__ float g_tup[(size_t)2 * T_SEQ * N_TOT * HID];
__device__ float g_repre[N_TOT * HID];
__device__ float g_sen_s[NBAG * HID];
__device__ float g_loss_part[NBAG];
__device__ unsigned int g_bar;   // global step barrier counter (zeroed per launch)

// ---------------- ptx helpers ----------------
__device__ __forceinline__ uint32_t smem_u32(const void *p) {
    uint32_t a;
    asm("{ .reg .u64 t; cvta.to.shared.u64 t, %1; cvt.u32.u64 %0, t; }" : "=r"(a) : "l"(p));
    return a;
}
#define BULK_G2S(dst, src, bytes, mbar)                                               \
    asm volatile(                                                                     \
        "cp.async.bulk.shared::cluster.global.mbarrier::complete_tx::bytes "          \
        "[%0], [%1], %2, [%3];"                                                       \
        :: "r"((uint32_t)(dst)), "l"(src), "r"((uint32_t)(bytes)),                    \
           "r"((uint32_t)(mbar)) : "memory")
#define MBARRIER_INIT(mb, cnt) \
    asm volatile("mbarrier.init.shared.b64 [%0], %1;" :: "r"((uint32_t)(mb)), "r"((uint32_t)(cnt)) : "memory")
#define MBARRIER_EXPECT_TX(mb, tx) \
    asm volatile("mbarrier.arrive.expect_tx.shared.b64 _, [%0], %1;" :: "r"((uint32_t)(mb)), "r"((uint32_t)(tx)) : "memory")
#define MBARRIER_ARRIVE(mb) \
    asm volatile("mbarrier.arrive.shared.b64 _, [%0];" :: "r"((uint32_t)(mb)) : "memory")
#define FENCE_ASYNC_SHARED() asm volatile("fence.proxy.async.shared::cta;" ::: "memory")
#define MBARRIER_WAIT_PARITY(mb, ph) do {                                             \
    uint32_t _m = (uint32_t)(mb); uint32_t _p = (uint32_t)(ph); uint32_t _d;          \
    asm volatile("{\n\t.reg .pred p;\n\t"                                             \
        "mbarrier.try_wait.parity.acquire.cta.shared::cta.b64 p, [%1], %2;\n\t"       \
        "selp.b32 %0, 1, 0, p;\n\t}" : "=r"(_d) : "r"(_m), "r"(_p) : "memory");       \
    if (!_d) {                                                                        \
        asm volatile("{\n\t.reg .pred P1;\n\t"                                        \
            "WL_%=:\n\t"                                                              \
            "mbarrier.try_wait.parity.acquire.cta.shared::cta.b64 P1, [%0], %1, 0x989680;\n\t" \
            "@P1 bra.uni WD_%=;\n\tbra.uni WL_%=;\n\tWD_%=:\n\t}"                     \
            :: "r"(_m), "r"(_p) : "memory");                                          \
    }                                                                                 \
} while (0)
#define LDSM4(r, a)                                                                   \
    asm volatile("ldmatrix.sync.aligned.m8n8.x4.shared.b16 {%0,%1,%2,%3}, [%4];"      \
                 : "=r"((r)[0]), "=r"((r)[1]), "=r"((r)[2]), "=r"((r)[3]) : "r"(a))
#define MMA16816(c, a, b0, b1)                                                        \
    asm volatile("mma.sync.aligned.m16n8k16.row.col.f32.bf16.bf16.f32 "               \
                 "{%0,%1,%2,%3},{%4,%5,%6,%7},{%8,%9},{%0,%1,%2,%3};"                 \
                 : "+f"((c)[0]), "+f"((c)[1]), "+f"((c)[2]), "+f"((c)[3])             \
                 : "r"((a)[0]), "r"((a)[1]), "r"((a)[2]), "r"((a)[3]), "r"(b0), "r"(b1))

__device__ __forceinline__ uint32_t pack2(__nv_bfloat16 a, __nv_bfloat16 b) {
    unsigned short ra = *(unsigned short *)&a, rb = *(unsigned short *)&b;
    return (uint32_t)ra | ((uint32_t)rb << 16);
}
__device__ __forceinline__ uint32_t swz(int row, int seg) {
    return (uint32_t)row * 64u + (uint32_t)((seg ^ ((row >> 1) & 3)) << 4);
}
__device__ __forceinline__ uint32_t swz_elem(int row, int kc) {
    return (swz(row, kc >> 3) + (uint32_t)(kc & 7) * 2u) >> 1;
}
// fast gate math (error ~1e-6, far under 1e-3 budget)
__device__ __forceinline__ float fsigmoid(float x) {
    return __fdividef(1.f, 1.f + __expf(-x));
}
__device__ __forceinline__ float ftanh(float x) {
    x = fminf(fmaxf(x, -15.f), 15.f);
    float e = __expf(2.f * x);
    return __fdividef(e - 1.f, e + 1.f);
}

// ---------------- prep kernels ----------------
__global__ void zero_kernel() {
    size_t i = (size_t)blockIdx.x * blockDim.x + threadIdx.x;
    size_t nh = (size_t)2 * 2 * 2 * 8 * N_TOT * 32 / 2;
    if (i < nh) ((uint32_t *)g_hbf)[i] = 0u;
    if (i < (size_t)2 * 2 * 256 * N_TOT) g_hT[i] = 0.f;
    if (i == 0) g_bar = 0u;
}

__global__ void prep_w_kernel(const float *__restrict__ Wihf, const float *__restrict__ Whhf,
                              const float *__restrict__ Wihb, const float *__restrict__ Whhb) {
    int idx = blockIdx.x * blockDim.x + threadIdx.x;
    if (idx >= 2 * 4 * 10 * 192 * 32) return;
    int kc = idx & 31;
    int r = (idx >> 5) % 192;
    int rest = idx / (192 * 32);
    int c = rest % 10;
    int jt = (rest / 10) & 3;
    int dir = rest / 40;
    const float *Wih = dir ? Wihb : Wihf;
    const float *Whh = dir ? Whhb : Whhf;
    int j = jt * 64 + r / 3;
    int g = r % 3;
    float v = 0.f;
    if (j < HID) {
        if (c < 2) {
            int k = c * 32 + kc;
            if (k < DIN) v = Wih[(g * HID + j) * DIN + k];
        } else {
            int kh = (c - 2) * 32 + kc;
            if (kh < HID) v = Whh[(g * HID + j) * HID + kh];
        }
    }
    __nv_bfloat16 hi = __float2bfloat16(v);
    __nv_bfloat16 lo = __float2bfloat16(v - __bfloat162float(hi));
    uint32_t off = swz_elem(r, kc);
    size_t b0 = (((size_t)(dir * 4 + jt) * 2 + 0) * 10 + c) * (192 * 32);
    size_t b1 = (((size_t)(dir * 4 + jt) * 2 + 1) * 10 + c) * (192 * 32);
    g_Wt[b0 + off] = hi;
    g_Wt[b1 + off] = lo;
}

__global__ void gather_kernel(const int *__restrict__ sent, const int *__restrict__ p1,
                              const int *__restrict__ p2, const float *__restrict__ wemb,
                              const float *__restrict__ p1t, const float *__restrict__ p2t) {
    size_t idx = (size_t)blockIdx.x * blockDim.x + threadIdx.x;
    if (idx >= (size_t)N_TOT * T_SEQ * 64) return;
    int k = (int)(idx & 63);
    size_t nt = idx >> 6;
    int t = (int)(nt % T_SEQ);
    int n = (int)(nt / T_SEQ);
    float v = 0.f;
    if (k < EMB_W) v = wemb[(size_t)sent[n * T_SEQ + t] * EMB_W + k];
    else if (k < EMB_W + 5) v = p1t[p1[n * T_SEQ + t] * 5 + (k - EMB_W)];
    else if (k < DIN) v = p2t[p2[n * T_SEQ + t] * 5 + (k - EMB_W - 5)];
    __nv_bfloat16 hi = __float2bfloat16(v);
    __nv_bfloat16 lo = __float2bfloat16(v - __bfloat162float(hi));
    int chunk = k >> 5, kc = k & 31;
    uint32_t off = swz_elem(n, kc);
    size_t b0 = (((size_t)t * 2 + 0) * 2 + chunk) * (N_TOT * 32);
    size_t b1 = (((size_t)t * 2 + 1) * 2 + chunk) * (N_TOT * 32);
    g_embsp[b0 + off] = hi;
    g_embsp[b1 + off] = lo;
}

// ---------------- persistent GRU (all 70 steps, device-wide step barrier) ----
__global__ void __launch_bounds__(NTHREADS, 1) gru_persistent_kernel(
    const float *__restrict__ bihf, const float *__restrict__ bhhf,
    const float *__restrict__ bihb, const float *__restrict__ bhhb) {
    extern __shared__ char dsm[];
    const int mtile = blockIdx.x & 15;
    const int jt = (blockIdx.x >> 4) & 3;
    const int dir = blockIdx.x >> 6;
    const int n0 = mtile * 128;
    const int tid = threadIdx.x;
    const int lane = tid & 31, wid = tid >> 5;
    const int warpM = wid & 3, warpN = wid >> 2;
    const float *bih = dir ? bihb : bihf;
    const float *bhh = dir ? bhhb : bhhf;

    const uint32_t base = smem_u32(dsm);
    float *dumpIN = (float *)(dsm + DUMP_OFF);
    __shared__ float bs[4][64];
    __shared__ __align__(8) unsigned long long mbar[6];   // full[3], empty[3]
    const uint32_t mbF = smem_u32(mbar);
    const uint32_t mbE = mbF + 24;

    if (tid < 64) {
        int j = jt * 64 + tid;
        bool ok = j < HID;
        bs[0][tid] = ok ? (bih[j] + bhh[j]) : 0.f;
        bs[1][tid] = ok ? (bih[HID + j] + bhh[HID + j]) : 0.f;
        bs[2][tid] = ok ? bih[2 * HID + j] : 0.f;
        bs[3][tid] = ok ? bhh[2 * HID + j] : 0.f;
    }
    if (tid == 0) {
        MBARRIER_INIT(mbF, 1);
        MBARRIER_INIT(mbF + 8, 1);
        MBARRIER_INIT(mbF + 16, 1);
        MBARRIER_INIT(mbE, 16);
        MBARRIER_INIT(mbE + 8, 16);
        MBARRIER_INIT(mbE + 16, 16);
        FENCE_ASYNC_SHARED();
    }
    __syncthreads();

    const __nv_bfloat16 *wbase = g_Wt + (size_t)(dir * 4 + jt) * 2 * 10 * (192 * 32);

    // arm global chunk q (q = step*10 + c). Continuous ring parity over all 700 chunks.
    auto arm = [&](int q) {
        if (q >= 3) MBARRIER_WAIT_PARITY(mbE + (uint32_t)(q % 3) * 8, ((q / 3) + 1) & 1);
        int sp = q / 10, c = q % 10;
        int tp = dir ? (T_SEQ - 1 - sp) : sp;
        int bufin = sp & 1;
        uint32_t st = base + (uint32_t)(q % 3) * STAGE_B;
        uint32_t mb = mbF + (uint32_t)(q % 3) * 8;
        MBARRIER_EXPECT_TX(mb, STAGE_B);
#pragma unroll
        for (int part = 0; part < 2; part++) {
            const __nv_bfloat16 *Ap;
            if (c < 2)
                Ap = g_embsp + (((size_t)tp * 2 + part) * 2 + c) * (N_TOT * 32) + (size_t)n0 * 32;
            else
                Ap = g_hbf + ((((size_t)(bufin * 2 + dir) * 2 + part) * 8) + (c - 2)) * (N_TOT * 32) + (size_t)n0 * 32;
            BULK_G2S(st + part * A_LO_OFF, Ap, 8192, mb);
            const __nv_bfloat16 *Bp = wbase + ((size_t)part * 10 + c) * (192 * 32);
            BULK_G2S(st + B_HI_OFF + part * B_PART, Bp, B_PART, mb);
        }
    };

    if (tid == 0) { arm(0); arm(1); arm(2); }

    const int laneR = lane & 15;
    const int laneHi = lane >> 4;
    const int gr = lane >> 2, lc = lane & 3;

    uint32_t ah[2][2][4], al[2][2][4];
    auto ldsmA = [&](int buf, int q, int ks) {
        uint32_t sA = base + (uint32_t)(q % 3) * STAGE_B;
#pragma unroll
        for (int mi = 0; mi < 2; mi++) {
            int row = warpM * 32 + mi * 16 + laneR;
            uint32_t off = swz(row, ks * 2 + laneHi);
            LDSM4(ah[buf][mi], sA + off);
            LDSM4(al[buf][mi], sA + A_LO_OFF + off);
        }
    };

    for (int s = 0; s < T_SEQ; s++) {
        const int t = dir ? (T_SEQ - 1 - s) : s;
        const int bufi = s & 1, bufo = (s + 1) & 1;
        const int qb = s * 10;

        float acc[2][6][4];
#pragma unroll
        for (int mi = 0; mi < 2; mi++)
#pragma unroll
            for (int ni = 0; ni < 6; ni++)
#pragma unroll
                for (int q = 0; q < 4; q++) acc[mi][ni][q] = 0.f;

        MBARRIER_WAIT_PARITY(mbF + (uint32_t)(qb % 3) * 8, (qb / 3) & 1);
        ldsmA(0, qb, 0);
#pragma unroll
        for (int g = 0; g < 20; g++) {
            const int c = g >> 1, ks = g & 1;
            const int q = qb + c;
            const int buf = g & 1;
            uint32_t bh[3][4], bl[3][4];
            {
                uint32_t sB = base + (uint32_t)(q % 3) * STAGE_B + B_HI_OFF;
#pragma unroll
                for (int np = 0; np < 3; np++) {
                    int row = warpN * 48 + np * 16 + laneR;
                    uint32_t off = swz(row, ks * 2 + laneHi);
                    LDSM4(bh[np], sB + off);
                    LDSM4(bl[np], sB + B_PART + off);
                }
            }
            if (g < 19) {
                const int gn = g + 1, cn = gn >> 1, ksn = gn & 1;
                const int qn = qb + cn;
                if (ksn == 0) MBARRIER_WAIT_PARITY(mbF + (uint32_t)(qn % 3) * 8, (qn / 3) & 1);
                ldsmA(buf ^ 1, qn, ksn);
            }
#pragma unroll
            for (int pass = 0; pass < 3; pass++) {
                const uint32_t(*aa)[4] = (pass == 2) ? al[buf] : ah[buf];
#pragma unroll
                for (int np = 0; np < 3; np++) {
                    const uint32_t *bb = (pass == 1) ? bl[np] : bh[np];
#pragma unroll
                    for (int mi = 0; mi < 2; mi++) {
                        MMA16816(acc[mi][np * 2], aa[mi], bb[0], bb[2]);
                        MMA16816(acc[mi][np * 2 + 1], aa[mi], bb[1], bb[3]);
                    }
                }
            }
            if (ks == 1) {
                if (lane == 0) MBARRIER_ARRIVE(mbE + (uint32_t)(q % 3) * 8);
                if (tid == 0 && c + 3 < 10) arm(q + 3);   // same-step h chunks only
            }
            if (g == 3) {
                // emb phase done: move i_n slots (col%3==2) to dumpIN, zero them
#pragma unroll
                for (int mi = 0; mi < 2; mi++)
#pragma unroll
                    for (int ni = 0; ni < 6; ni++)
#pragma unroll
                        for (int b = 0; b < 2; b++) {
                            int col = warpN * 48 + ni * 8 + lc * 2 + b;
                            if (col % 3 == 2) {
                                int jl = col / 3;
                                int m0 = warpM * 32 + mi * 16 + gr;
                                dumpIN[jl * 132 + m0] = acc[mi][ni][b];
                                dumpIN[jl * 132 + m0 + 8] = acc[mi][ni][b + 2];
                                acc[mi][ni][b] = 0.f;
                                acc[mi][ni][b + 2] = 0.f;
                            }
                        }
            }
        }

        __syncthreads();   // all warps done with ring slots; reuse for D staging
        float *D2 = (float *)dsm;   // [192 col][132]
#pragma unroll
        for (int mi = 0; mi < 2; mi++)
#pragma unroll
            for (int ni = 0; ni < 6; ni++) {
                int col0 = warpN * 48 + ni * 8 + lc * 2;
                int m0 = warpM * 32 + mi * 16 + gr;
                D2[col0 * 132 + m0] = acc[mi][ni][0];
                D2[(col0 + 1) * 132 + m0] = acc[mi][ni][1];
                D2[col0 * 132 + m0 + 8] = acc[mi][ni][2];
                D2[(col0 + 1) * 132 + m0 + 8] = acc[mi][ni][3];
            }
        __syncthreads();

        // gates: 512 work items (64 jl x 8 nsegs of 16)
        {
            int jl = tid >> 3, nseg = tid & 7;
            int j = jt * 64 + jl;
            int nb = nseg * 16;
            float br = bs[0][jl], bz = bs[1][jl], bin = bs[2][jl], bhn = bs[3][jl];
            const float4 *holdp = (const float4 *)(g_hT + ((size_t)(bufi * 2 + dir) * 256 + j) * N_TOT + n0 + nb);
            float4 *hnewp = (float4 *)(g_hT + ((size_t)(bufo * 2 + dir) * 256 + j) * N_TOT + n0 + nb);
            const float *Dr = D2 + (jl * 3 + 0) * 132 + nb;
            const float *Dz = D2 + (jl * 3 + 1) * 132 + nb;
            const float *Dn = D2 + (jl * 3 + 2) * 132 + nb;
            const float *Di = dumpIN + jl * 132 + nb;
            float hv[16];
#pragma unroll
            for (int v4 = 0; v4 < 4; v4++) {
                float4 hold4 = holdp[v4];
                float ho[4] = {hold4.x, hold4.y, hold4.z, hold4.w};
                float4 out4;
                float *o = (float *)&out4;
#pragma unroll
                for (int q = 0; q < 4; q++) {
                    int i = v4 * 4 + q;
                    float r = fsigmoid(Dr[i] + br);
                    float z = fsigmoid(Dz[i] + bz);
                    float nn = ftanh(Di[i] + bin + r * (Dn[i] + bhn));
                    float h = (1.f - z) * nn + z * ho[q];
                    hv[i] = h;
                    o[q] = h;
                }
                hnewp[v4] = out4;
            }
#pragma unroll
            for (int i = 0; i < 16; i++) D2[(jl * 3) * 132 + nb + i] = hv[i];
        }
        __syncthreads();

        // writeout: tup fp32 [n][j]; h bf16 hi/lo chunk-major pre-swizzled
        {
            float *tupp = g_tup + (((size_t)dir * T_SEQ + t) * N_TOT) * HID;
#pragma unroll
            for (int it = 0; it < 2; it++) {
                int l = it * NTHREADS + tid;   // 0..1023
                int nl = l >> 3, seg8 = l & 7;
                int n = n0 + nl;
                int jb = seg8 * 8;
                float v[8];
#pragma unroll
                for (int q = 0; q < 8; q++) v[q] = D2[((jb + q) * 3) * 132 + nl];
#pragma unroll
                for (int q = 0; q < 8; q++) {
                    int j = jt * 64 + jb + q;
                    if (j < HID) tupp[(size_t)n * HID + j] = v[q];
                }
                __nv_bfloat16 hi[8], lo[8];
#pragma unroll
                for (int q = 0; q < 8; q++) {
                    hi[q] = __float2bfloat16(v[q]);
                    lo[q] = __float2bfloat16(v[q] - __bfloat162float(hi[q]));
                }
                uint4 vh, vl;
                vh.x = pack2(hi[0], hi[1]); vh.y = pack2(hi[2], hi[3]);
                vh.z = pack2(hi[4], hi[5]); vh.w = pack2(hi[6], hi[7]);
                vl.x = pack2(lo[0], lo[1]); vl.y = pack2(lo[2], lo[3]);
                vl.z = pack2(lo[4], lo[5]); vl.w = pack2(lo[6], lo[7]);
                int hch = jt * 2 + (seg8 >> 2);
                uint32_t off = swz(n, seg8 & 3);
                __nv_bfloat16 *hb0 = g_hbf + ((((size_t)(bufo * 2 + dir) * 2 + 0) * 8 + hch) * N_TOT) * 32;
                __nv_bfloat16 *hb1 = g_hbf + ((((size_t)(bufo * 2 + dir) * 2 + 1) * 8 + hch) * N_TOT) * 32;
                *(uint4 *)((char *)hb0 + off) = vh;
                *(uint4 *)((char *)hb1 + off) = vl;
            }
        }

        // ---- device-wide step barrier, then arm next step's first 3 chunks ----
        if (s + 1 < T_SEQ) {
            __threadfence();
            __syncthreads();
            if (tid == 0) {
                unsigned target = 128u * (unsigned)(s + 1);
                atomicAdd(&g_bar, 1u);
                while (*((volatile unsigned int *)&g_bar) < target) {
                    __nanosleep(64);
                }
            }
            __syncthreads();
            __threadfence();
            if (tid == 0) {
                arm(qb + 10);
                arm(qb + 11);
                arm(qb + 12);
            }
        }
    }
}

// ---------------- word-level attention ----------------
__global__ void __launch_bounds__(256) attn_kernel(const float *__restrict__ att_w) {
    const int n = blockIdx.x;
    const int tid = threadIdx.x;
    __shared__ float xsum[HID];
    __shared__ float red[8];
    __shared__ float s_bc;
    float acc = 0.f, m = -1e30f, denom = 0.f;
    float w = (tid < HID) ? att_w[tid] : 0.f;
    for (int t = 0; t < T_SEQ; t++) {
        if (tid < HID) {
            size_t i0 = (((size_t)0 * T_SEQ + t) * N_TOT + n) * HID + tid;
            size_t i1 = (((size_t)1 * T_SEQ + t) * N_TOT + n) * HID + tid;
            xsum[tid] = g_tup[i0] + g_tup[i1];
        }
        __syncthreads();
        float part = (tid < HID) ? ftanh(xsum[tid]) * w : 0.f;
#pragma unroll
        for (int o = 16; o > 0; o >>= 1) part += __shfl_down_sync(0xffffffffu, part, o);
        if ((tid & 31) == 0) red[tid >> 5] = part;
        __syncthreads();
        if (tid == 0) {
            float sm = 0.f;
#pragma unroll
            for (int q = 0; q < 8; q++) sm += red[q];
            s_bc = sm;
        }
        __syncthreads();
        float st = s_bc;
        float mn = fmaxf(m, st);
        float cc = __expf(m - mn), e = __expf(st - mn);
        denom = denom * cc + e;
        if (tid < HID) acc = acc * cc + e * xsum[tid];
        m = mn;
        __syncthreads();
    }
    if (tid < HID) g_repre[n * HID + tid] = ftanh(acc / denom);
}

// ---------------- bag attention ----------------
__global__ void __launch_bounds__(256) bag_kernel(const float *__restrict__ sen_a,
                                                  const float *__restrict__ sen_r) {
    const int b = blockIdx.x;
    const int tid = threadIdx.x;
    __shared__ float R[BAGSZ][HID];
    __shared__ float sv[BAGSZ];
    __shared__ float alpha[BAGSZ];
    for (int l = tid; l < BAGSZ * HID; l += 256) {
        int i = l / HID, j = l % HID;
        R[i][j] = g_repre[(b * BAGSZ + i) * HID + j];
    }
    __syncthreads();
    int wid = tid >> 5, lane = tid & 31;
    for (int i = wid; i < BAGSZ; i += 8) {
        float p = 0.f;
        for (int j = lane; j < HID; j += 32) p += R[i][j] * sen_a[j] * sen_r[j];
#pragma unroll
        for (int o = 16; o > 0; o >>= 1) p += __shfl_down_sync(0xffffffffu, p, o);
        if (lane == 0) sv[i] = p;
    }
    __syncthreads();
    if (tid == 0) {
        float mm = -1e30f;
        for (int i = 0; i < BAGSZ; i++) mm = fmaxf(mm, sv[i]);
        float ss = 0.f;
        for (int i = 0; i < BAGSZ; i++) { float e = expf(sv[i] - mm); alpha[i] = e; ss += e; }
        for (int i = 0; i < BAGSZ; i++) alpha[i] /= ss;
    }
    __syncthreads();
    for (int j = tid; j < HID; j += 256) {
        float a = 0.f;
#pragma unroll 4
        for (int i = 0; i < BAGSZ; i++) a += alpha[i] * R[i][j];
        g_sen_s[b * HID + j] = a;
    }
}

// ---------------- logits / prob / bce / acc ----------------
__global__ void __launch_bounds__(128) logits_kernel(const float *__restrict__ rel,
                                                     const float *__restrict__ sen_d,
                                                     const float *__restrict__ y,
                                                     float *__restrict__ out) {
    const int b = blockIdx.x;
    const int tid = threadIdx.x;
    __shared__ float ss[HID];
    __shared__ float lg[NREL];
    __shared__ float mmax;
    __shared__ int amax;
    __shared__ float dsum;
    for (int j = tid; j < HID; j += 128) ss[j] = g_sen_s[b * HID + j];
    __syncthreads();
    if (tid < NREL) {
        float a = sen_d[tid];
        const float *row = rel + (size_t)tid * HID;
        for (int j = 0; j < HID; j++) a += ss[j] * row[j];
        lg[tid] = a;
    }
    __syncthreads();
    if (tid == 0) {
        float mm = lg[0]; int am = 0;
        for (int c = 1; c < NREL; c++) if (lg[c] > mm) { mm = lg[c]; am = c; }
        mmax = mm; amax = am;
        float sum = 0.f;
        for (int c = 0; c < NREL; c++) sum += expf(lg[c] - mm);
        dsum = sum;
    }
    __syncthreads();
    if (tid < NREL) out[1 + NBAG + b * NREL + tid] = expf(lg[tid] - mmax) / dsum;
    if (tid == 0) {
        float loss = 0.f; int lab = 0;
        for (int c = 0; c < NREL; c++) {
            float l = lg[c], yv = y[b * NREL + c];
            loss += fmaxf(l, 0.f) - l * yv + log1pf(expf(-fabsf(l)));
            if (yv > 0.5f) lab = c;
        }
        g_loss_part[b] = loss / (float)NREL;
        out[1 + b] = (amax == lab) ? 1.f : 0.f;
    }
}

__global__ void loss_sum_kernel(float *__restrict__ out) {
    if (threadIdx.x == 0) {
        float s = 0.f;
        for (int b = 0; b < NBAG; b++) s += g_loss_part[b];
        out[0] = s;
    }
}

// ---------------- launch ----------------
extern "C" void kernel_launch(void *const *d_in, const int *in_sizes, int n_in,
                              void *d_out, int out_size) {
    const int *sentence = (const int *)d_in[0];
    const int *pos1 = (const int *)d_in[1];
    const int *pos2 = (const int *)d_in[2];
    const float *y_batch = (const float *)d_in[4];
    const float *word_emb = (const float *)d_in[5];
    const float *p1t = (const float *)d_in[6];
    const float *p2t = (const float *)d_in[7];
    const float *Wihf = (const float *)d_in[8];
    const float *Whhf = (const float *)d_in[9];
    const float *bihf = (const float *)d_in[10];
    const float *bhhf = (const float *)d_in[11];
    const float *Wihb = (const float *)d_in[12];
    const float *Whhb = (const float *)d_in[13];
    const float *bihb = (const float *)d_in[14];
    const float *bhhb = (const float *)d_in[15];
    const float *attw = (const float *)d_in[16];
    const float *sena = (const float *)d_in[17];
    const float *senr = (const float *)d_in[18];
    const float *rel = (const float *)d_in[19];
    const float *send = (const float *)d_in[20];
    float *out = (float *)d_out;

    cudaFuncSetAttribute(gru_persistent_kernel, cudaFuncAttributeMaxDynamicSharedMemorySize, SMEM_DYN);

    zero_kernel<<<(int)(((size_t)2 * 2 * 2 * 8 * N_TOT * 32 / 2 + 255) / 256), 256>>>();
    prep_w_kernel<<<(2 * 4 * 10 * 192 * 32 + 255) / 256, 256>>>(Wihf, Whhf, Wihb, Whhb);
    gather_kernel<<<(int)(((size_t)N_TOT * T_SEQ * 64 + 255) / 256), 256>>>(
        sentence, pos1, pos2, word_emb, p1t, p2t);

    gru_persistent_kernel<<<128, NTHREADS, SMEM_DYN>>>(bihf, bhhf, bihb, bhhb);

    attn_kernel<<<N_TOT, 256>>>(attw);
    bag_kernel<<<NBAG, 256>>>(sena, senr);
    logits_kernel<<<NBAG, 128>>>(rel, send, y_batch, out);
    loss_sum_kernel<<<1, 32>>>(out);
}

// round 13
// speedup vs baseline: 1.3496x; 1.2977x over previous
#include <cuda_runtime.h>
#include <cuda_fp16.h>
#include <math.h>
#include <stdint.h>

#define N_TOT 2048
#define T_SEQ 70
#define HID   230
#define DIN   60
#define EMB_W 50
#define NBAG  64
#define BAGSZ 32
#define NREL  100

// GRU persistent: 128 CTAs (1/SM), 70 steps in-kernel, 4-CTA group barriers.
// Per CTA: M=128, N=192 (64j x 3 gates), K=320 in 10 chunks of 32.
// fp16 2-pass: x split hi/lo fp16, weights single fp16.
// stage: A_hi[8K] A_lo[8K] B[12K] = 28672 B, 3-slot TMA ring.
#define NTHREADS 512
#define STAGE_B  28672
#define A_LO_OFF 8192
#define B_OFF    16384
#define DUMP_OFF 101376                     // after D2 region (192*132*4)
#define HP_OFF   (DUMP_OFF + 64 * 132 * 4)  // 135168
#define SMEM_DYN (HP_OFF + 64 * 128 * 4)    // 167936

// ---------------- device scratch (pre-swizzled, chunk-major, fp16) ----------
__device__ __align__(128) __half g_Wt[(size_t)2 * 4 * 10 * 192 * 32];
__device__ __align__(128) __half g_embsp[(size_t)T_SEQ * 2 * 2 * N_TOT * 32]; // [t][part][chunk2]
__device__ __align__(128) __half g_hbf[(size_t)2 * 2 * 2 * 8 * N_TOT * 32];   // [buf][dir][part][chunk8]
__device__ float g_tup[(size_t)2 * T_SEQ * N_TOT * HID];
__device__ float g_repre[N_TOT * HID];
__device__ float g_sen_s[NBAG * HID];
__device__ float g_loss_part[NBAG];
__device__ unsigned int g_bars[32];

// ---------------- ptx helpers ----------------
__device__ __forceinline__ uint32_t smem_u32(const void *p) {
    uint32_t a;
    asm("{ .reg .u64 t; cvta.to.shared.u64 t, %1; cvt.u32.u64 %0, t; }" : "=r"(a) : "l"(p));
    return a;
}
#define BULK_G2S(dst, src, bytes, mbar)                                               \
    asm volatile(                                                                     \
        "cp.async.bulk.shared::cluster.global.mbarrier::complete_tx::bytes "          \
        "[%0], [%1], %2, [%3];"                                                       \
        :: "r"((uint32_t)(dst)), "l"(src), "r"((uint32_t)(bytes)),                    \
           "r"((uint32_t)(mbar)) : "memory")
#define MBARRIER_INIT(mb, cnt) \
    asm volatile("mbarrier.init.shared.b64 [%0], %1;" :: "r"((uint32_t)(mb)), "r"((uint32_t)(cnt)) : "memory")
#define MBARRIER_EXPECT_TX(mb, tx) \
    asm volatile("mbarrier.arrive.expect_tx.shared.b64 _, [%0], %1;" :: "r"((uint32_t)(mb)), "r"((uint32_t)(tx)) : "memory")
#define MBARRIER_ARRIVE(mb) \
    asm volatile("mbarrier.arrive.shared.b64 _, [%0];" :: "r"((uint32_t)(mb)) : "memory")
#define FENCE_ASYNC_SHARED() asm volatile("fence.proxy.async.shared::cta;" ::: "memory")
#define MBARRIER_WAIT_PARITY(mb, ph) do {                                             \
    uint32_t _m = (uint32_t)(mb); uint32_t _p = (uint32_t)(ph); uint32_t _d;          \
    asm volatile("{\n\t.reg .pred p;\n\t"                                             \
        "mbarrier.try_wait.parity.acquire.cta.shared::cta.b64 p, [%1], %2;\n\t"       \
        "selp.b32 %0, 1, 0, p;\n\t}" : "=r"(_d) : "r"(_m), "r"(_p) : "memory");       \
    if (!_d) {                                                                        \
        asm volatile("{\n\t.reg .pred P1;\n\t"                                        \
            "WL_%=:\n\t"                                                              \
            "mbarrier.try_wait.parity.acquire.cta.shared::cta.b64 P1, [%0], %1, 0x989680;\n\t" \
            "@P1 bra.uni WD_%=;\n\tbra.uni WL_%=;\n\tWD_%=:\n\t}"                     \
            :: "r"(_m), "r"(_p) : "memory");                                          \
    }                                                                                 \
} while (0)
#define LDSM4(r, a)                                                                   \
    asm volatile("ldmatrix.sync.aligned.m8n8.x4.shared.b16 {%0,%1,%2,%3}, [%4];"      \
                 : "=r"((r)[0]), "=r"((r)[1]), "=r"((r)[2]), "=r"((r)[3]) : "r"(a))
#define MMA16816H(c, a, b0, b1)                                                       \
    asm volatile("mma.sync.aligned.m16n8k16.row.col.f32.f16.f16.f32 "                 \
                 "{%0,%1,%2,%3},{%4,%5,%6,%7},{%8,%9},{%0,%1,%2,%3};"                 \
                 : "+f"((c)[0]), "+f"((c)[1]), "+f"((c)[2]), "+f"((c)[3])             \
                 : "r"((a)[0]), "r"((a)[1]), "r"((a)[2]), "r"((a)[3]), "r"(b0), "r"(b1))

__device__ __forceinline__ uint32_t pack2h(__half a, __half b) {
    unsigned short ra = *(unsigned short *)&a, rb = *(unsigned short *)&b;
    return (uint32_t)ra | ((uint32_t)rb << 16);
}
__device__ __forceinline__ uint32_t swz(int row, int seg) {
    return (uint32_t)row * 64u + (uint32_t)((seg ^ ((row >> 1) & 3)) << 4);
}
__device__ __forceinline__ uint32_t swz_elem(int row, int kc) {
    return (swz(row, kc >> 3) + (uint32_t)(kc & 7) * 2u) >> 1;
}
__device__ __forceinline__ float fsigmoid(float x) {
    return __fdividef(1.f, 1.f + __expf(-x));
}
__device__ __forceinline__ float ftanh(float x) {
    x = fminf(fmaxf(x, -15.f), 15.f);
    float e = __expf(2.f * x);
    return __fdividef(e - 1.f, e + 1.f);
}

// ---------------- prep kernels ----------------
__global__ void zero_kernel() {
    size_t i = (size_t)blockIdx.x * blockDim.x + threadIdx.x;
    size_t nh = (size_t)2 * 2 * 2 * 8 * N_TOT * 32 / 2;
    if (i < nh) ((uint32_t *)g_hbf)[i] = 0u;
    if (i < 32) g_bars[i] = 0u;
}

// weights -> [dir][jt(4)][chunk(10)] contiguous 12288B swizzled fp16; row = j_local*3+gate
__global__ void prep_w_kernel(const float *__restrict__ Wihf, const float *__restrict__ Whhf,
                              const float *__restrict__ Wihb, const float *__restrict__ Whhb) {
    int idx = blockIdx.x * blockDim.x + threadIdx.x;
    if (idx >= 2 * 4 * 10 * 192 * 32) return;
    int kc = idx & 31;
    int r = (idx >> 5) % 192;
    int rest = idx / (192 * 32);
    int c = rest % 10;
    int jt = (rest / 10) & 3;
    int dir = rest / 40;
    const float *Wih = dir ? Wihb : Wihf;
    const float *Whh = dir ? Whhb : Whhf;
    int j = jt * 64 + r / 3;
    int g = r % 3;
    float v = 0.f;
    if (j < HID) {
        if (c < 2) {
            int k = c * 32 + kc;
            if (k < DIN) v = Wih[(g * HID + j) * DIN + k];
        } else {
            int kh = (c - 2) * 32 + kc;
            if (kh < HID) v = Whh[(g * HID + j) * HID + kh];
        }
    }
    uint32_t off = swz_elem(r, kc);
    g_Wt[((size_t)(dir * 4 + jt) * 10 + c) * (192 * 32) + off] = __float2half(v);
}

__global__ void gather_kernel(const int *__restrict__ sent, const int *__restrict__ p1,
                              const int *__restrict__ p2, const float *__restrict__ wemb,
                              const float *__restrict__ p1t, const float *__restrict__ p2t) {
    size_t idx = (size_t)blockIdx.x * blockDim.x + threadIdx.x;
    if (idx >= (size_t)N_TOT * T_SEQ * 64) return;
    int k = (int)(idx & 63);
    size_t nt = idx >> 6;
    int t = (int)(nt % T_SEQ);
    int n = (int)(nt / T_SEQ);
    float v = 0.f;
    if (k < EMB_W) v = wemb[(size_t)sent[n * T_SEQ + t] * EMB_W + k];
    else if (k < EMB_W + 5) v = p1t[p1[n * T_SEQ + t] * 5 + (k - EMB_W)];
    else if (k < DIN) v = p2t[p2[n * T_SEQ + t] * 5 + (k - EMB_W - 5)];
    __half hi = __float2half(v);
    __half lo = __float2half(v - __half2float(hi));
    int chunk = k >> 5, kc = k & 31;
    uint32_t off = swz_elem(n, kc);
    g_embsp[(((size_t)t * 2 + 0) * 2 + chunk) * (N_TOT * 32) + off] = hi;
    g_embsp[(((size_t)t * 2 + 1) * 2 + chunk) * (N_TOT * 32) + off] = lo;
}

// ---------------- persistent GRU ----------------
__global__ void __launch_bounds__(NTHREADS, 1) gru_persistent_kernel(
    const float *__restrict__ bihf, const float *__restrict__ bhhf,
    const float *__restrict__ bihb, const float *__restrict__ bhhb) {
    extern __shared__ char dsm[];
    const int mtile = blockIdx.x & 15;
    const int jt = (blockIdx.x >> 4) & 3;
    const int dir = blockIdx.x >> 6;
    const int grp = (dir << 4) | mtile;
    const int n0 = mtile * 128;
    const int tid = threadIdx.x;
    const int lane = tid & 31, wid = tid >> 5;
    const int warpM = wid & 3, warpN = wid >> 2;
    const float *bih = dir ? bihb : bihf;
    const float *bhh = dir ? bhhb : bhhf;

    const uint32_t base = smem_u32(dsm);
    float *dumpIN = (float *)(dsm + DUMP_OFF);
    float *hP = (float *)(dsm + HP_OFF);        // persistent fp32 h [64 jl][128 n]
    __shared__ float bs[4][64];
    __shared__ __align__(8) unsigned long long mbar[6];
    const uint32_t mbF = smem_u32(mbar);
    const uint32_t mbE = mbF + 24;

    if (tid < 64) {
        int j = jt * 64 + tid;
        bool ok = j < HID;
        bs[0][tid] = ok ? (bih[j] + bhh[j]) : 0.f;
        bs[1][tid] = ok ? (bih[HID + j] + bhh[HID + j]) : 0.f;
        bs[2][tid] = ok ? bih[2 * HID + j] : 0.f;
        bs[3][tid] = ok ? bhh[2 * HID + j] : 0.f;
    }
#pragma unroll
    for (int it = 0; it < 16; it++) hP[it * NTHREADS + tid] = 0.f;
    if (tid == 0) {
        MBARRIER_INIT(mbF, 1);
        MBARRIER_INIT(mbF + 8, 1);
        MBARRIER_INIT(mbF + 16, 1);
        MBARRIER_INIT(mbE, 16);
        MBARRIER_INIT(mbE + 8, 16);
        MBARRIER_INIT(mbE + 16, 16);
        FENCE_ASYNC_SHARED();
    }
    __syncthreads();

    const __half *wbase = g_Wt + (size_t)(dir * 4 + jt) * 10 * (192 * 32);

    auto arm = [&](int q) {
        if (q >= 3) MBARRIER_WAIT_PARITY(mbE + (uint32_t)(q % 3) * 8, ((q / 3) + 1) & 1);
        int sp = q / 10, c = q % 10;
        int tp = dir ? (T_SEQ - 1 - sp) : sp;
        int bufin = sp & 1;
        uint32_t st = base + (uint32_t)(q % 3) * STAGE_B;
        uint32_t mb = mbF + (uint32_t)(q % 3) * 8;
        MBARRIER_EXPECT_TX(mb, STAGE_B);
#pragma unroll
        for (int part = 0; part < 2; part++) {
            const __half *Ap;
            if (c < 2)
                Ap = g_embsp + (((size_t)tp * 2 + part) * 2 + c) * (N_TOT * 32) + (size_t)n0 * 32;
            else
                Ap = g_hbf + ((((size_t)(bufin * 2 + dir) * 2 + part) * 8) + (c - 2)) * (N_TOT * 32) + (size_t)n0 * 32;
            BULK_G2S(st + part * A_LO_OFF, Ap, 8192, mb);
        }
        BULK_G2S(st + B_OFF, wbase + (size_t)c * (192 * 32), 12288, mb);
    };

    if (tid == 0) { arm(0); arm(1); arm(2); }

    const int laneR = lane & 15;
    const int laneHi = lane >> 4;
    const int gr = lane >> 2, lc = lane & 3;

    uint32_t ah[2][2][4], al[2][2][4];
    auto ldsmA = [&](int buf, int q, int ks) {
        uint32_t sA = base + (uint32_t)(q % 3) * STAGE_B;
#pragma unroll
        for (int mi = 0; mi < 2; mi++) {
            int row = warpM * 32 + mi * 16 + laneR;
            uint32_t off = swz(row, ks * 2 + laneHi);
            LDSM4(ah[buf][mi], sA + off);
            LDSM4(al[buf][mi], sA + A_LO_OFF + off);
        }
    };

    for (int s = 0; s < T_SEQ; s++) {
        const int t = dir ? (T_SEQ - 1 - s) : s;
        const int bufo = (s + 1) & 1;
        const int qb = s * 10;

        float acc[2][6][4];
#pragma unroll
        for (int mi = 0; mi < 2; mi++)
#pragma unroll
            for (int ni = 0; ni < 6; ni++)
#pragma unroll
                for (int q = 0; q < 4; q++) acc[mi][ni][q] = 0.f;

        MBARRIER_WAIT_PARITY(mbF + (uint32_t)(qb % 3) * 8, (qb / 3) & 1);
        ldsmA(0, qb, 0);
#pragma unroll
        for (int g = 0; g < 20; g++) {
            const int c = g >> 1, ks = g & 1;
            const int q = qb + c;
            const int buf = g & 1;
            uint32_t bq[3][4];
            {
                uint32_t sB = base + (uint32_t)(q % 3) * STAGE_B + B_OFF;
#pragma unroll
                for (int np = 0; np < 3; np++) {
                    int row = warpN * 48 + np * 16 + laneR;
                    LDSM4(bq[np], sB + swz(row, ks * 2 + laneHi));
                }
            }
            if (g < 19) {
                const int gn = g + 1, cn = gn >> 1, ksn = gn & 1;
                const int qn = qb + cn;
                if (ksn == 0) MBARRIER_WAIT_PARITY(mbF + (uint32_t)(qn % 3) * 8, (qn / 3) & 1);
                ldsmA(buf ^ 1, cn + qb == qn ? qn : qn, ksn);
            }
            // 24 MMAs, pass-outer: same-acc spacing = 12
#pragma unroll
            for (int pass = 0; pass < 2; pass++) {
                const uint32_t(*aa)[4] = pass ? al[buf] : ah[buf];
#pragma unroll
                for (int np = 0; np < 3; np++) {
#pragma unroll
                    for (int mi = 0; mi < 2; mi++) {
                        MMA16816H(acc[mi][np * 2], aa[mi], bq[np][0], bq[np][2]);
                        MMA16816H(acc[mi][np * 2 + 1], aa[mi], bq[np][1], bq[np][3]);
                    }
                }
            }
            if (ks == 1) {
                if (lane == 0) MBARRIER_ARRIVE(mbE + (uint32_t)(q % 3) * 8);
                if (tid == 0 && c + 3 < 10) arm(q + 3);
            }
            if (g == 3) {
#pragma unroll
                for (int mi = 0; mi < 2; mi++)
#pragma unroll
                    for (int ni = 0; ni < 6; ni++)
#pragma unroll
                        for (int b = 0; b < 2; b++) {
                            int col = warpN * 48 + ni * 8 + lc * 2 + b;
                            if (col % 3 == 2) {
                                int jl = col / 3;
                                int m0 = warpM * 32 + mi * 16 + gr;
                                dumpIN[jl * 132 + m0] = acc[mi][ni][b];
                                dumpIN[jl * 132 + m0 + 8] = acc[mi][ni][b + 2];
                                acc[mi][ni][b] = 0.f;
                                acc[mi][ni][b + 2] = 0.f;
                            }
                        }
            }
        }

        __syncthreads();
        float *D2 = (float *)dsm;   // [192 col][132]
#pragma unroll
        for (int mi = 0; mi < 2; mi++)
#pragma unroll
            for (int ni = 0; ni < 6; ni++) {
                int col0 = warpN * 48 + ni * 8 + lc * 2;
                int m0 = warpM * 32 + mi * 16 + gr;
                D2[col0 * 132 + m0] = acc[mi][ni][0];
                D2[(col0 + 1) * 132 + m0] = acc[mi][ni][1];
                D2[col0 * 132 + m0 + 8] = acc[mi][ni][2];
                D2[(col0 + 1) * 132 + m0 + 8] = acc[mi][ni][3];
            }
        __syncthreads();

        // gates: h persistent in smem
        {
            int jl = tid >> 3, nseg = tid & 7;
            int nb = nseg * 16;
            float br = bs[0][jl], bz = bs[1][jl], bin = bs[2][jl], bhn = bs[3][jl];
            const float *Dr = D2 + (jl * 3 + 0) * 132 + nb;
            const float *Dz = D2 + (jl * 3 + 1) * 132 + nb;
            const float *Dn = D2 + (jl * 3 + 2) * 132 + nb;
            const float *Di = dumpIN + jl * 132 + nb;
            float *hp = hP + jl * 128 + nb;
            float hv[16];
#pragma unroll
            for (int i = 0; i < 16; i++) {
                float r = fsigmoid(Dr[i] + br);
                float z = fsigmoid(Dz[i] + bz);
                float nn = ftanh(Di[i] + bin + r * (Dn[i] + bhn));
                float h = (1.f - z) * nn + z * hp[i];
                hv[i] = h;
            }
#pragma unroll
            for (int i = 0; i < 16; i++) hp[i] = hv[i];
#pragma unroll
            for (int i = 0; i < 16; i++) D2[(jl * 3) * 132 + nb + i] = hv[i];
        }
        __syncthreads();

        // writeout: tup fp32 [n][j] (float2), hbf fp16 hi/lo chunk-major
        {
            float *tupp = g_tup + (((size_t)dir * T_SEQ + t) * N_TOT) * HID;
#pragma unroll
            for (int it = 0; it < 2; it++) {
                int l = it * NTHREADS + tid;
                int nl = l >> 3, seg8 = l & 7;
                int n = n0 + nl;
                int jb = seg8 * 8;
                float v[8];
#pragma unroll
                for (int q = 0; q < 8; q++) v[q] = D2[((jb + q) * 3) * 132 + nl];
                {
                    int jg = jt * 64 + jb;
                    float *tp = tupp + (size_t)n * HID + jg;
#pragma unroll
                    for (int q2 = 0; q2 < 4; q2++) {
                        int jg2 = jg + q2 * 2;
                        if (jg2 + 1 < HID) {
                            *(float2 *)(tp + q2 * 2) = make_float2(v[q2 * 2], v[q2 * 2 + 1]);
                        } else if (jg2 < HID) {
                            tp[q2 * 2] = v[q2 * 2];
                        }
                    }
                }
                __half hi[8], lo[8];
#pragma unroll
                for (int q = 0; q < 8; q++) {
                    hi[q] = __float2half(v[q]);
                    lo[q] = __float2half(v[q] - __half2float(hi[q]));
                }
                uint4 vh, vl;
                vh.x = pack2h(hi[0], hi[1]); vh.y = pack2h(hi[2], hi[3]);
                vh.z = pack2h(hi[4], hi[5]); vh.w = pack2h(hi[6], hi[7]);
                vl.x = pack2h(lo[0], lo[1]); vl.y = pack2h(lo[2], lo[3]);
                vl.z = pack2h(lo[4], lo[5]); vl.w = pack2h(lo[6], lo[7]);
                int hch = jt * 2 + (seg8 >> 2);
                uint32_t off = swz(n, seg8 & 3);
                __half *hb0 = g_hbf + ((((size_t)(bufo * 2 + dir) * 2 + 0) * 8 + hch) * N_TOT) * 32;
                __half *hb1 = g_hbf + ((((size_t)(bufo * 2 + dir) * 2 + 1) * 8 + hch) * N_TOT) * 32;
                *(uint4 *)((char *)hb0 + off) = vh;
                *(uint4 *)((char *)hb1 + off) = vl;
            }
        }

        // ---- group barrier (4 CTAs sharing (mtile,dir)), then arm next step ----
        if (s + 1 < T_SEQ) {
            __threadfence();
            __syncthreads();
            if (tid == 0) {
                unsigned target = 4u * (unsigned)(s + 1);
                atomicAdd(&g_bars[grp], 1u);
                while (*((volatile unsigned int *)&g_bars[grp]) < target) {
                    __nanosleep(32);
                }
            }
            __syncthreads();
            __threadfence();
            if (tid == 0) {
                arm(qb + 10);
                arm(qb + 11);
                arm(qb + 12);
            }
        }
    }
}

// ---------------- word-level attention ----------------
__global__ void __launch_bounds__(256) attn_kernel(const float *__restrict__ att_w) {
    const int n = blockIdx.x;
    const int tid = threadIdx.x;
    __shared__ float xsum[HID];
    __shared__ float red[8];
    __shared__ float s_bc;
    float acc = 0.f, m = -1e30f, denom = 0.f;
    float w = (tid < HID) ? att_w[tid] : 0.f;
    for (int t = 0; t < T_SEQ; t++) {
        if (tid < HID) {
            size_t i0 = (((size_t)0 * T_SEQ + t) * N_TOT + n) * HID + tid;
            size_t i1 = (((size_t)1 * T_SEQ + t) * N_TOT + n) * HID + tid;
            xsum[tid] = g_tup[i0] + g_tup[i1];
        }
        __syncthreads();
        float part = (tid < HID) ? ftanh(xsum[tid]) * w : 0.f;
#pragma unroll
        for (int o = 16; o > 0; o >>= 1) part += __shfl_down_sync(0xffffffffu, part, o);
        if ((tid & 31) == 0) red[tid >> 5] = part;
        __syncthreads();
        if (tid == 0) {
            float sm = 0.f;
#pragma unroll
            for (int q = 0; q < 8; q++) sm += red[q];
            s_bc = sm;
        }
        __syncthreads();
        float st = s_bc;
        float mn = fmaxf(m, st);
        float cc = __expf(m - mn), e = __expf(st - mn);
        denom = denom * cc + e;
        if (tid < HID) acc = acc * cc + e * xsum[tid];
        m = mn;
        __syncthreads();
    }
    if (tid < HID) g_repre[n * HID + tid] = ftanh(acc / denom);
}

// ---------------- bag attention ----------------
__global__ void __launch_bounds__(256) bag_kernel(const float *__restrict__ sen_a,
                                                  const float *__restrict__ sen_r) {
    const int b = blockIdx.x;
    const int tid = threadIdx.x;
    __shared__ float R[BAGSZ][HID];
    __shared__ float sv[BAGSZ];
    __shared__ float alpha[BAGSZ];
    for (int l = tid; l < BAGSZ * HID; l += 256) {
        int i = l / HID, j = l % HID;
        R[i][j] = g_repre[(b * BAGSZ + i) * HID + j];
    }
    __syncthreads();
    int wid = tid >> 5, lane = tid & 31;
    for (int i = wid; i < BAGSZ; i += 8) {
        float p = 0.f;
        for (int j = lane; j < HID; j += 32) p += R[i][j] * sen_a[j] * sen_r[j];
#pragma unroll
        for (int o = 16; o > 0; o >>= 1) p += __shfl_down_sync(0xffffffffu, p, o);
        if (lane == 0) sv[i] = p;
    }
    __syncthreads();
    if (tid == 0) {
        float mm = -1e30f;
        for (int i = 0; i < BAGSZ; i++) mm = fmaxf(mm, sv[i]);
        float ss = 0.f;
        for (int i = 0; i < BAGSZ; i++) { float e = expf(sv[i] - mm); alpha[i] = e; ss += e; }
        for (int i = 0; i < BAGSZ; i++) alpha[i] /= ss;
    }
    __syncthreads();
    for (int j = tid; j < HID; j += 256) {
        float a = 0.f;
#pragma unroll 4
        for (int i = 0; i < BAGSZ; i++) a += alpha[i] * R[i][j];
        g_sen_s[b * HID + j] = a;
    }
}

// ---------------- logits / prob / bce / acc ----------------
__global__ void __launch_bounds__(128) logits_kernel(const float *__restrict__ rel,
                                                     const float *__restrict__ sen_d,
                                                     const float *__restrict__ y,
                                                     float *__restrict__ out) {
    const int b = blockIdx.x;
    const int tid = threadIdx.x;
    __shared__ float ss[HID];
    __shared__ float lg[NREL];
    __shared__ float mmax;
    __shared__ int amax;
    __shared__ float dsum;
    for (int j = tid; j < HID; j += 128) ss[j] = g_sen_s[b * HID + j];
    __syncthreads();
    if (tid < NREL) {
        float a = sen_d[tid];
        const float *row = rel + (size_t)tid * HID;
        for (int j = 0; j < HID; j++) a += ss[j] * row[j];
        lg[tid] = a;
    }
    __syncthreads();
    if (tid == 0) {
        float mm = lg[0]; int am = 0;
        for (int c = 1; c < NREL; c++) if (lg[c] > mm) { mm = lg[c]; am = c; }
        mmax = mm; amax = am;
        float sum = 0.f;
        for (int c = 0; c < NREL; c++) sum += expf(lg[c] - mm);
        dsum = sum;
    }
    __syncthreads();
    if (tid < NREL) out[1 + NBAG + b * NREL + tid] = expf(lg[tid] - mmax) / dsum;
    if (tid == 0) {
        float loss = 0.f; int lab = 0;
        for (int c = 0; c < NREL; c++) {
            float l = lg[c], yv = y[b * NREL + c];
            loss += fmaxf(l, 0.f) - l * yv + log1pf(expf(-fabsf(l)));
            if (yv > 0.5f) lab = c;
        }
        g_loss_part[b] = loss / (float)NREL;
        out[1 + b] = (amax == lab) ? 1.f : 0.f;
    }
}

__global__ void loss_sum_kernel(float *__restrict__ out) {
    if (threadIdx.x == 0) {
        float s = 0.f;
        for (int b = 0; b < NBAG; b++) s += g_loss_part[b];
        out[0] = s;
    }
}

// ---------------- launch ----------------
extern "C" void kernel_launch(void *const *d_in, const int *in_sizes, int n_in,
                              void *d_out, int out_size) {
    const int *sentence = (const int *)d_in[0];
    const int *pos1 = (const int *)d_in[1];
    const int *pos2 = (const int *)d_in[2];
    const float *y_batch = (const float *)d_in[4];
    const float *word_emb = (const float *)d_in[5];
    const float *p1t = (const float *)d_in[6];
    const float *p2t = (const float *)d_in[7];
    const float *Wihf = (const float *)d_in[8];
    const float *Whhf = (const float *)d_in[9];
    const float *bihf = (const float *)d_in[10];
    const float *bhhf = (const float *)d_in[11];
    const float *Wihb = (const float *)d_in[12];
    const float *Whhb = (const float *)d_in[13];
    const float *bihb = (const float *)d_in[14];
    const float *bhhb = (const float *)d_in[15];
    const float *attw = (const float *)d_in[16];
    const float *sena = (const float *)d_in[17];
    const float *senr = (const float *)d_in[18];
    const float *rel = (const float *)d_in[19];
    const float *send = (const float *)d_in[20];
    float *out = (float *)d_out;

    cudaFuncSetAttribute(gru_persistent_kernel, cudaFuncAttributeMaxDynamicSharedMemorySize, SMEM_DYN);

    zero_kernel<<<(int)(((size_t)2 * 2 * 2 * 8 * N_TOT * 32 / 2 + 255) / 256), 256>>>();
    prep_w_kernel<<<(2 * 4 * 10 * 192 * 32 + 255) / 256, 256>>>(Wihf, Whhf, Wihb, Whhb);
    gather_kernel<<<(int)(((size_t)N_TOT * T_SEQ * 64 + 255) / 256), 256>>>(
        sentence, pos1, pos2, word_emb, p1t, p2t);

    gru_persistent_kernel<<<128, NTHREADS, SMEM_DYN>>>(bihf, bhhf, bihb, bhhb);

    attn_kernel<<<N_TOT, 256>>>(attw);
    bag_kernel<<<NBAG, 256>>>(sena, senr);
    logits_kernel<<<NBAG, 128>>>(rel, send, y_batch, out);
    loss_sum_kernel<<<1, 32>>>(out);
}

// round 14
// speedup vs baseline: 1.7709x; 1.3122x over previous
#include <cuda_runtime.h>
#include <cuda_fp16.h>
#include <math.h>
#include <stdint.h>

#define N_TOT 2048
#define T_SEQ 70
#define HID   230
#define DIN   60
#define EMB_W 50
#define NBAG  64
#define BAGSZ 32
#define NREL  100

// GRU persistent: 128 CTAs (1/SM), 70 steps in-kernel, 4-CTA group barriers.
// Per CTA: M=128, N=192 (64j x 3 gates), K=320 in 10 chunks of 32.
// Pure fp16 1-pass (x and w fp16; fp32 recurrence state exact in smem).
// stage: A[8K] B[12K] = 20480 B, 3-slot TMA ring.
#define NTHREADS 512
#define STAGE_B  20480
#define B_OFF    8192
#define DUMP_OFF 101376                     // after D2 region (192*132*4)
#define HP_OFF   (DUMP_OFF + 64 * 132 * 4)  // 135168
#define SMEM_DYN (HP_OFF + 64 * 128 * 4)    // 167936

// ---------------- device scratch (pre-swizzled, chunk-major, fp16) ----------
__device__ __align__(128) __half g_Wt[(size_t)2 * 4 * 10 * 192 * 32];
__device__ __align__(128) __half g_embsp[(size_t)T_SEQ * 2 * N_TOT * 32]; // [t][chunk2]
__device__ __align__(128) __half g_hbf[(size_t)2 * 2 * 8 * N_TOT * 32];   // [buf][dir][chunk8]
__device__ float g_tup[(size_t)2 * T_SEQ * N_TOT * HID];
__device__ float g_repre[N_TOT * HID];
__device__ float g_sen_s[NBAG * HID];
__device__ float g_loss_part[NBAG];
__device__ unsigned int g_bars[32];

// ---------------- ptx helpers ----------------
__device__ __forceinline__ uint32_t smem_u32(const void *p) {
    uint32_t a;
    asm("{ .reg .u64 t; cvta.to.shared.u64 t, %1; cvt.u32.u64 %0, t; }" : "=r"(a) : "l"(p));
    return a;
}
#define BULK_G2S(dst, src, bytes, mbar)                                               \
    asm volatile(                                                                     \
        "cp.async.bulk.shared::cluster.global.mbarrier::complete_tx::bytes "          \
        "[%0], [%1], %2, [%3];"                                                       \
        :: "r"((uint32_t)(dst)), "l"(src), "r"((uint32_t)(bytes)),                    \
           "r"((uint32_t)(mbar)) : "memory")
#define MBARRIER_INIT(mb, cnt) \
    asm volatile("mbarrier.init.shared.b64 [%0], %1;" :: "r"((uint32_t)(mb)), "r"((uint32_t)(cnt)) : "memory")
#define MBARRIER_EXPECT_TX(mb, tx) \
    asm volatile("mbarrier.arrive.expect_tx.shared.b64 _, [%0], %1;" :: "r"((uint32_t)(mb)), "r"((uint32_t)(tx)) : "memory")
#define MBARRIER_ARRIVE(mb) \
    asm volatile("mbarrier.arrive.shared.b64 _, [%0];" :: "r"((uint32_t)(mb)) : "memory")
#define FENCE_ASYNC_SHARED() asm volatile("fence.proxy.async.shared::cta;" ::: "memory")
#define MBARRIER_WAIT_PARITY(mb, ph) do {                                             \
    uint32_t _m = (uint32_t)(mb); uint32_t _p = (uint32_t)(ph); uint32_t _d;          \
    asm volatile("{\n\t.reg .pred p;\n\t"                                             \
        "mbarrier.try_wait.parity.acquire.cta.shared::cta.b64 p, [%1], %2;\n\t"       \
        "selp.b32 %0, 1, 0, p;\n\t}" : "=r"(_d) : "r"(_m), "r"(_p) : "memory");       \
    if (!_d) {                                                                        \
        asm volatile("{\n\t.reg .pred P1;\n\t"                                        \
            "WL_%=:\n\t"                                                              \
            "mbarrier.try_wait.parity.acquire.cta.shared::cta.b64 P1, [%0], %1, 0x989680;\n\t" \
            "@P1 bra.uni WD_%=;\n\tbra.uni WL_%=;\n\tWD_%=:\n\t}"                     \
            :: "r"(_m), "r"(_p) : "memory");                                          \
    }                                                                                 \
} while (0)
#define LDSM4(r, a)                                                                   \
    asm volatile("ldmatrix.sync.aligned.m8n8.x4.shared.b16 {%0,%1,%2,%3}, [%4];"      \
                 : "=r"((r)[0]), "=r"((r)[1]), "=r"((r)[2]), "=r"((r)[3]) : "r"(a))
#define MMA16816H(c, a, b0, b1)                                                       \
    asm volatile("mma.sync.aligned.m16n8k16.row.col.f32.f16.f16.f32 "                 \
                 "{%0,%1,%2,%3},{%4,%5,%6,%7},{%8,%9},{%0,%1,%2,%3};"                 \
                 : "+f"((c)[0]), "+f"((c)[1]), "+f"((c)[2]), "+f"((c)[3])             \
                 : "r"((a)[0]), "r"((a)[1]), "r"((a)[2]), "r"((a)[3]), "r"(b0), "r"(b1))

__device__ __forceinline__ uint32_t pack2h(__half a, __half b) {
    unsigned short ra = *(unsigned short *)&a, rb = *(unsigned short *)&b;
    return (uint32_t)ra | ((uint32_t)rb << 16);
}
__device__ __forceinline__ uint32_t swz(int row, int seg) {
    return (uint32_t)row * 64u + (uint32_t)((seg ^ ((row >> 1) & 3)) << 4);
}
__device__ __forceinline__ uint32_t swz_elem(int row, int kc) {
    return (swz(row, kc >> 3) + (uint32_t)(kc & 7) * 2u) >> 1;
}
__device__ __forceinline__ float fsigmoid(float x) {
    return __fdividef(1.f, 1.f + __expf(-x));
}
__device__ __forceinline__ float ftanh(float x) {
    x = fminf(fmaxf(x, -15.f), 15.f);
    float e = __expf(2.f * x);
    return __fdividef(e - 1.f, e + 1.f);
}

// ---------------- prep kernels ----------------
__global__ void zero_kernel() {
    size_t i = (size_t)blockIdx.x * blockDim.x + threadIdx.x;
    size_t nh = (size_t)2 * 2 * 8 * N_TOT * 32 / 2;
    if (i < nh) ((uint32_t *)g_hbf)[i] = 0u;
    if (i < 32) g_bars[i] = 0u;
}

// weights -> [dir][jt(4)][chunk(10)] contiguous 12288B swizzled fp16; row = j_local*3+gate
__global__ void prep_w_kernel(const float *__restrict__ Wihf, const float *__restrict__ Whhf,
                              const float *__restrict__ Wihb, const float *__restrict__ Whhb) {
    int idx = blockIdx.x * blockDim.x + threadIdx.x;
    if (idx >= 2 * 4 * 10 * 192 * 32) return;
    int kc = idx & 31;
    int r = (idx >> 5) % 192;
    int rest = idx / (192 * 32);
    int c = rest % 10;
    int jt = (rest / 10) & 3;
    int dir = rest / 40;
    const float *Wih = dir ? Wihb : Wihf;
    const float *Whh = dir ? Whhb : Whhf;
    int j = jt * 64 + r / 3;
    int g = r % 3;
    float v = 0.f;
    if (j < HID) {
        if (c < 2) {
            int k = c * 32 + kc;
            if (k < DIN) v = Wih[(g * HID + j) * DIN + k];
        } else {
            int kh = (c - 2) * 32 + kc;
            if (kh < HID) v = Whh[(g * HID + j) * HID + kh];
        }
    }
    uint32_t off = swz_elem(r, kc);
    g_Wt[((size_t)(dir * 4 + jt) * 10 + c) * (192 * 32) + off] = __float2half(v);
}

__global__ void gather_kernel(const int *__restrict__ sent, const int *__restrict__ p1,
                              const int *__restrict__ p2, const float *__restrict__ wemb,
                              const float *__restrict__ p1t, const float *__restrict__ p2t) {
    size_t idx = (size_t)blockIdx.x * blockDim.x + threadIdx.x;
    if (idx >= (size_t)N_TOT * T_SEQ * 64) return;
    int k = (int)(idx & 63);
    size_t nt = idx >> 6;
    int t = (int)(nt % T_SEQ);
    int n = (int)(nt / T_SEQ);
    float v = 0.f;
    if (k < EMB_W) v = wemb[(size_t)sent[n * T_SEQ + t] * EMB_W + k];
    else if (k < EMB_W + 5) v = p1t[p1[n * T_SEQ + t] * 5 + (k - EMB_W)];
    else if (k < DIN) v = p2t[p2[n * T_SEQ + t] * 5 + (k - EMB_W - 5)];
    int chunk = k >> 5, kc = k & 31;
    uint32_t off = swz_elem(n, kc);
    g_embsp[((size_t)t * 2 + chunk) * (N_TOT * 32) + off] = __float2half(v);
}

// ---------------- persistent GRU ----------------
__global__ void __launch_bounds__(NTHREADS, 1) gru_persistent_kernel(
    const float *__restrict__ bihf, const float *__restrict__ bhhf,
    const float *__restrict__ bihb, const float *__restrict__ bhhb) {
    extern __shared__ char dsm[];
    const int mtile = blockIdx.x & 15;
    const int jt = (blockIdx.x >> 4) & 3;
    const int dir = blockIdx.x >> 6;
    const int grp = (dir << 4) | mtile;
    const int n0 = mtile * 128;
    const int tid = threadIdx.x;
    const int lane = tid & 31, wid = tid >> 5;
    const int warpM = wid & 3, warpN = wid >> 2;
    const float *bih = dir ? bihb : bihf;
    const float *bhh = dir ? bhhb : bhhf;

    const uint32_t base = smem_u32(dsm);
    float *dumpIN = (float *)(dsm + DUMP_OFF);
    float *hP = (float *)(dsm + HP_OFF);        // persistent fp32 h [64 jl][128 n]
    __shared__ float bs[4][64];
    __shared__ __align__(8) unsigned long long mbar[6];
    const uint32_t mbF = smem_u32(mbar);
    const uint32_t mbE = mbF + 24;

    if (tid < 64) {
        int j = jt * 64 + tid;
        bool ok = j < HID;
        bs[0][tid] = ok ? (bih[j] + bhh[j]) : 0.f;
        bs[1][tid] = ok ? (bih[HID + j] + bhh[HID + j]) : 0.f;
        bs[2][tid] = ok ? bih[2 * HID + j] : 0.f;
        bs[3][tid] = ok ? bhh[2 * HID + j] : 0.f;
    }
#pragma unroll
    for (int it = 0; it < 16; it++) hP[it * NTHREADS + tid] = 0.f;
    if (tid == 0) {
        MBARRIER_INIT(mbF, 1);
        MBARRIER_INIT(mbF + 8, 1);
        MBARRIER_INIT(mbF + 16, 1);
        MBARRIER_INIT(mbE, 16);
        MBARRIER_INIT(mbE + 8, 16);
        MBARRIER_INIT(mbE + 16, 16);
        FENCE_ASYNC_SHARED();
    }
    __syncthreads();

    const __half *wbase = g_Wt + (size_t)(dir * 4 + jt) * 10 * (192 * 32);

    auto arm = [&](int q) {
        if (q >= 3) MBARRIER_WAIT_PARITY(mbE + (uint32_t)(q % 3) * 8, ((q / 3) + 1) & 1);
        int sp = q / 10, c = q % 10;
        int tp = dir ? (T_SEQ - 1 - sp) : sp;
        int bufin = sp & 1;
        uint32_t st = base + (uint32_t)(q % 3) * STAGE_B;
        uint32_t mb = mbF + (uint32_t)(q % 3) * 8;
        MBARRIER_EXPECT_TX(mb, STAGE_B);
        const __half *Ap;
        if (c < 2)
            Ap = g_embsp + ((size_t)tp * 2 + c) * (N_TOT * 32) + (size_t)n0 * 32;
        else
            Ap = g_hbf + (((size_t)(bufin * 2 + dir)) * 8 + (c - 2)) * (N_TOT * 32) + (size_t)n0 * 32;
        BULK_G2S(st, Ap, 8192, mb);
        BULK_G2S(st + B_OFF, wbase + (size_t)c * (192 * 32), 12288, mb);
    };

    if (tid == 0) { arm(0); arm(1); arm(2); }

    const int laneR = lane & 15;
    const int laneHi = lane >> 4;
    const int gr = lane >> 2, lc = lane & 3;

    uint32_t ah[2][2][4];
    auto ldsmA = [&](int buf, int q, int ks) {
        uint32_t sA = base + (uint32_t)(q % 3) * STAGE_B;
#pragma unroll
        for (int mi = 0; mi < 2; mi++) {
            int row = warpM * 32 + mi * 16 + laneR;
            LDSM4(ah[buf][mi], sA + swz(row, ks * 2 + laneHi));
        }
    };

    for (int s = 0; s < T_SEQ; s++) {
        const int t = dir ? (T_SEQ - 1 - s) : s;
        const int bufo = (s + 1) & 1;
        const int qb = s * 10;

        float acc[2][6][4];
#pragma unroll
        for (int mi = 0; mi < 2; mi++)
#pragma unroll
            for (int ni = 0; ni < 6; ni++)
#pragma unroll
                for (int q = 0; q < 4; q++) acc[mi][ni][q] = 0.f;

        MBARRIER_WAIT_PARITY(mbF + (uint32_t)(qb % 3) * 8, (qb / 3) & 1);
        ldsmA(0, qb, 0);
#pragma unroll
        for (int g = 0; g < 20; g++) {
            const int c = g >> 1, ks = g & 1;
            const int q = qb + c;
            const int buf = g & 1;
            uint32_t bq[3][4];
            {
                uint32_t sB = base + (uint32_t)(q % 3) * STAGE_B + B_OFF;
#pragma unroll
                for (int np = 0; np < 3; np++) {
                    int row = warpN * 48 + np * 16 + laneR;
                    LDSM4(bq[np], sB + swz(row, ks * 2 + laneHi));
                }
            }
            if (g < 19) {
                const int gn = g + 1, ksn = gn & 1;
                const int qn = qb + (gn >> 1);
                if (ksn == 0) MBARRIER_WAIT_PARITY(mbF + (uint32_t)(qn % 3) * 8, (qn / 3) & 1);
                ldsmA(buf ^ 1, qn, ksn);
            }
            // 12 MMAs; each acc updated once per stage
#pragma unroll
            for (int np = 0; np < 3; np++) {
#pragma unroll
                for (int mi = 0; mi < 2; mi++) {
                    MMA16816H(acc[mi][np * 2], ah[buf][mi], bq[np][0], bq[np][2]);
                    MMA16816H(acc[mi][np * 2 + 1], ah[buf][mi], bq[np][1], bq[np][3]);
                }
            }
            if (ks == 1) {
                if (lane == 0) MBARRIER_ARRIVE(mbE + (uint32_t)(q % 3) * 8);
                if (tid == 0 && c + 3 < 10) arm(q + 3);
            }
            if (g == 3) {
                // emb phase done: move i_n slots (col%3==2) to dumpIN, zero them
#pragma unroll
                for (int mi = 0; mi < 2; mi++)
#pragma unroll
                    for (int ni = 0; ni < 6; ni++)
#pragma unroll
                        for (int b = 0; b < 2; b++) {
                            int col = warpN * 48 + ni * 8 + lc * 2 + b;
                            if (col % 3 == 2) {
                                int jl = col / 3;
                                int m0 = warpM * 32 + mi * 16 + gr;
                                dumpIN[jl * 132 + m0] = acc[mi][ni][b];
                                dumpIN[jl * 132 + m0 + 8] = acc[mi][ni][b + 2];
                                acc[mi][ni][b] = 0.f;
                                acc[mi][ni][b + 2] = 0.f;
                            }
                        }
            }
        }

        __syncthreads();
        float *D2 = (float *)dsm;   // [192 col][132]
#pragma unroll
        for (int mi = 0; mi < 2; mi++)
#pragma unroll
            for (int ni = 0; ni < 6; ni++) {
                int col0 = warpN * 48 + ni * 8 + lc * 2;
                int m0 = warpM * 32 + mi * 16 + gr;
                D2[col0 * 132 + m0] = acc[mi][ni][0];
                D2[(col0 + 1) * 132 + m0] = acc[mi][ni][1];
                D2[col0 * 132 + m0 + 8] = acc[mi][ni][2];
                D2[(col0 + 1) * 132 + m0 + 8] = acc[mi][ni][3];
            }
        __syncthreads();

        // gates: h persistent in smem
        {
            int jl = tid >> 3, nseg = tid & 7;
            int nb = nseg * 16;
            float br = bs[0][jl], bz = bs[1][jl], bin = bs[2][jl], bhn = bs[3][jl];
            const float *Dr = D2 + (jl * 3 + 0) * 132 + nb;
            const float *Dz = D2 + (jl * 3 + 1) * 132 + nb;
            const float *Dn = D2 + (jl * 3 + 2) * 132 + nb;
            const float *Di = dumpIN + jl * 132 + nb;
            float *hp = hP + jl * 128 + nb;
            float hv[16];
#pragma unroll
            for (int i = 0; i < 16; i++) {
                float r = fsigmoid(Dr[i] + br);
                float z = fsigmoid(Dz[i] + bz);
                float nn = ftanh(Di[i] + bin + r * (Dn[i] + bhn));
                float h = (1.f - z) * nn + z * hp[i];
                hv[i] = h;
            }
#pragma unroll
            for (int i = 0; i < 16; i++) hp[i] = hv[i];
#pragma unroll
            for (int i = 0; i < 16; i++) D2[(jl * 3) * 132 + nb + i] = hv[i];
        }
        __syncthreads();

        // writeout: tup fp32 [n][j] (float2), hbf fp16 chunk-major
        {
            float *tupp = g_tup + (((size_t)dir * T_SEQ + t) * N_TOT) * HID;
#pragma unroll
            for (int it = 0; it < 2; it++) {
                int l = it * NTHREADS + tid;
                int nl = l >> 3, seg8 = l & 7;
                int n = n0 + nl;
                int jb = seg8 * 8;
                float v[8];
#pragma unroll
                for (int q = 0; q < 8; q++) v[q] = D2[((jb + q) * 3) * 132 + nl];
                {
                    int jg = jt * 64 + jb;
                    float *tp = tupp + (size_t)n * HID + jg;
#pragma unroll
                    for (int q2 = 0; q2 < 4; q2++) {
                        int jg2 = jg + q2 * 2;
                        if (jg2 + 1 < HID) {
                            *(float2 *)(tp + q2 * 2) = make_float2(v[q2 * 2], v[q2 * 2 + 1]);
                        } else if (jg2 < HID) {
                            tp[q2 * 2] = v[q2 * 2];
                        }
                    }
                }
                __half hh[8];
#pragma unroll
                for (int q = 0; q < 8; q++) hh[q] = __float2half(v[q]);
                uint4 vh;
                vh.x = pack2h(hh[0], hh[1]); vh.y = pack2h(hh[2], hh[3]);
                vh.z = pack2h(hh[4], hh[5]); vh.w = pack2h(hh[6], hh[7]);
                int hch = jt * 2 + (seg8 >> 2);
                uint32_t off = swz(n, seg8 & 3);
                __half *hb0 = g_hbf + (((size_t)(bufo * 2 + dir)) * 8 + hch) * (N_TOT * 32);
                *(uint4 *)((char *)hb0 + off) = vh;
            }
        }

        // ---- group barrier (4 CTAs sharing (mtile,dir)), then arm next step ----
        if (s + 1 < T_SEQ) {
            __threadfence();
            __syncthreads();
            if (tid == 0) {
                unsigned target = 4u * (unsigned)(s + 1);
                atomicAdd(&g_bars[grp], 1u);
                while (*((volatile unsigned int *)&g_bars[grp]) < target) {
                    __nanosleep(32);
                }
            }
            __syncthreads();
            __threadfence();
            if (tid == 0) {
                arm(qb + 10);
                arm(qb + 11);
                arm(qb + 12);
            }
        }
    }
}

// ---------------- word-level attention ----------------
__global__ void __launch_bounds__(256) attn_kernel(const float *__restrict__ att_w) {
    const int n = blockIdx.x;
    const int tid = threadIdx.x;
    __shared__ float xsum[HID];
    __shared__ float red[8];
    __shared__ float s_bc;
    float acc = 0.f, m = -1e30f, denom = 0.f;
    float w = (tid < HID) ? att_w[tid] : 0.f;
    for (int t = 0; t < T_SEQ; t++) {
        if (tid < HID) {
            size_t i0 = (((size_t)0 * T_SEQ + t) * N_TOT + n) * HID + tid;
            size_t i1 = (((size_t)1 * T_SEQ + t) * N_TOT + n) * HID + tid;
            xsum[tid] = g_tup[i0] + g_tup[i1];
        }
        __syncthreads();
        float part = (tid < HID) ? ftanh(xsum[tid]) * w : 0.f;
#pragma unroll
        for (int o = 16; o > 0; o >>= 1) part += __shfl_down_sync(0xffffffffu, part, o);
        if ((tid & 31) == 0) red[tid >> 5] = part;
        __syncthreads();
        if (tid == 0) {
            float sm = 0.f;
#pragma unroll
            for (int q = 0; q < 8; q++) sm += red[q];
            s_bc = sm;
        }
        __syncthreads();
        float st = s_bc;
        float mn = fmaxf(m, st);
        float cc = __expf(m - mn), e = __expf(st - mn);
        denom = denom * cc + e;
        if (tid < HID) acc = acc * cc + e * xsum[tid];
        m = mn;
        __syncthreads();
    }
    if (tid < HID) g_repre[n * HID + tid] = ftanh(acc / denom);
}

// ---------------- bag attention ----------------
__global__ void __launch_bounds__(256) bag_kernel(const float *__restrict__ sen_a,
                                                  const float *__restrict__ sen_r) {
    const int b = blockIdx.x;
    const int tid = threadIdx.x;
    __shared__ float R[BAGSZ][HID];
    __shared__ float sv[BAGSZ];
    __shared__ float alpha[BAGSZ];
    for (int l = tid; l < BAGSZ * HID; l += 256) {
        int i = l / HID, j = l % HID;
        R[i][j] = g_repre[(b * BAGSZ + i) * HID + j];
    }
    __syncthreads();
    int wid = tid >> 5, lane = tid & 31;
    for (int i = wid; i < BAGSZ; i += 8) {
        float p = 0.f;
        for (int j = lane; j < HID; j += 32) p += R[i][j] * sen_a[j] * sen_r[j];
#pragma unroll
        for (int o = 16; o > 0; o >>= 1) p += __shfl_down_sync(0xffffffffu, p, o);
        if (lane == 0) sv[i] = p;
    }
    __syncthreads();
    if (tid == 0) {
        float mm = -1e30f;
        for (int i = 0; i < BAGSZ; i++) mm = fmaxf(mm, sv[i]);
        float ss = 0.f;
        for (int i = 0; i < BAGSZ; i++) { float e = expf(sv[i] - mm); alpha[i] = e; ss += e; }
        for (int i = 0; i < BAGSZ; i++) alpha[i] /= ss;
    }
    __syncthreads();
    for (int j = tid; j < HID; j += 256) {
        float a = 0.f;
#pragma unroll 4
        for (int i = 0; i < BAGSZ; i++) a += alpha[i] * R[i][j];
        g_sen_s[b * HID + j] = a;
    }
}

// ---------------- logits / prob / bce / acc ----------------
__global__ void __launch_bounds__(128) logits_kernel(const float *__restrict__ rel,
                                                     const float *__restrict__ sen_d,
                                                     const float *__restrict__ y,
                                                     float *__restrict__ out) {
    const int b = blockIdx.x;
    const int tid = threadIdx.x;
    __shared__ float ss[HID];
    __shared__ float lg[NREL];
    __shared__ float mmax;
    __shared__ int amax;
    __shared__ float dsum;
    for (int j = tid; j < HID; j += 128) ss[j] = g_sen_s[b * HID + j];
    __syncthreads();
    if (tid < NREL) {
        float a = sen_d[tid];
        const float *row = rel + (size_t)tid * HID;
        for (int j = 0; j < HID; j++) a += ss[j] * row[j];
        lg[tid] = a;
    }
    __syncthreads();
    if (tid == 0) {
        float mm = lg[0]; int am = 0;
        for (int c = 1; c < NREL; c++) if (lg[c] > mm) { mm = lg[c]; am = c; }
        mmax = mm; amax = am;
        float sum = 0.f;
        for (int c = 0; c < NREL; c++) sum += expf(lg[c] - mm);
        dsum = sum;
    }
    __syncthreads();
    if (tid < NREL) out[1 + NBAG + b * NREL + tid] = expf(lg[tid] - mmax) / dsum;
    if (tid == 0) {
        float loss = 0.f; int lab = 0;
        for (int c = 0; c < NREL; c++) {
            float l = lg[c], yv = y[b * NREL + c];
            loss += fmaxf(l, 0.f) - l * yv + log1pf(expf(-fabsf(l)));
            if (yv > 0.5f) lab = c;
        }
        g_loss_part[b] = loss / (float)NREL;
        out[1 + b] = (amax == lab) ? 1.f : 0.f;
    }
}

__global__ void loss_sum_kernel(float *__restrict__ out) {
    if (threadIdx.x == 0) {
        float s = 0.f;
        for (int b = 0; b < NBAG; b++) s += g_loss_part[b];
        out[0] = s;
    }
}

// ---------------- launch ----------------
extern "C" void kernel_launch(void *const *d_in, const int *in_sizes, int n_in,
                              void *d_out, int out_size) {
    const int *sentence = (const int *)d_in[0];
    const int *pos1 = (const int *)d_in[1];
    const int *pos2 = (const int *)d_in[2];
    const float *y_batch = (const float *)d_in[4];
    const float *word_emb = (const float *)d_in[5];
    const float *p1t = (const float *)d_in[6];
    const float *p2t = (const float *)d_in[7];
    const float *Wihf = (const float *)d_in[8];
    const float *Whhf = (const float *)d_in[9];
    const float *bihf = (const float *)d_in[10];
    const float *bhhf = (const float *)d_in[11];
    const float *Wihb = (const float *)d_in[12];
    const float *Whhb = (const float *)d_in[13];
    const float *bihb = (const float *)d_in[14];
    const float *bhhb = (const float *)d_in[15];
    const float *attw = (const float *)d_in[16];
    const float *sena = (const float *)d_in[17];
    const float *senr = (const float *)d_in[18];
    const float *rel = (const float *)d_in[19];
    const float *send = (const float *)d_in[20];
    float *out = (float *)d_out;

    cudaFuncSetAttribute(gru_persistent_kernel, cudaFuncAttributeMaxDynamicSharedMemorySize, SMEM_DYN);

    zero_kernel<<<(int)(((size_t)2 * 2 * 8 * N_TOT * 32 / 2 + 255) / 256), 256>>>();
    prep_w_kernel<<<(2 * 4 * 10 * 192 * 32 + 255) / 256, 256>>>(Wihf, Whhf, Wihb, Whhb);
    gather_kernel<<<(int)(((size_t)N_TOT * T_SEQ * 64 + 255) / 256), 256>>>(
        sentence, pos1, pos2, word_emb, p1t, p2t);

    gru_persistent_kernel<<<128, NTHREADS, SMEM_DYN>>>(bihf, bhhf, bihb, bhhb);

    attn_kernel<<<N_TOT, 256>>>(attw);
    bag_kernel<<<NBAG, 256>>>(sena, senr);
    logits_kernel<<<NBAG, 128>>>(rel, send, y_batch, out);
    loss_sum_kernel<<<1, 32>>>(out);
}

// round 15
// speedup vs baseline: 2.0448x; 1.1547x over previous
#include <cuda_runtime.h>
#include <cuda_fp16.h>
#include <math.h>
#include <stdint.h>

#define N_TOT 2048
#define T_SEQ 70
#define HID   230
#define DIN   60
#define EMB_W 50
#define NBAG  64
#define BAGSZ 32
#define NREL  100
#define TPAD  232

// GRU persistent: 128 CTAs (1/SM), 70 steps in-kernel, 4-CTA group barriers.
// Per CTA: M=128, N=192 (64j x 3 gates), K=320 in 10 chunks of 32.
// Pure fp16 1-pass (x and w fp16; fp32 recurrence state exact in smem).
// stage: A[8K] B[12K] = 20480 B, 3-slot TMA ring.
#define NTHREADS 512
#define STAGE_B  20480
#define B_OFF    8192
#define DUMP_OFF 101376                     // after D2 region (192*132*4)
#define HP_OFF   (DUMP_OFF + 64 * 132 * 4)  // 135168
#define SMEM_DYN (HP_OFF + 64 * 128 * 4)    // 167936

// ---------------- device scratch (pre-swizzled, chunk-major, fp16) ----------
__device__ __align__(128) __half g_Wt[(size_t)2 * 4 * 10 * 192 * 32];
__device__ __align__(128) __half g_embsp[(size_t)T_SEQ * 2 * N_TOT * 32]; // [t][chunk2]
__device__ __align__(128) __half g_hbf[(size_t)2 * 2 * 8 * N_TOT * 32];   // [buf][dir][chunk8]
__device__ __align__(128) __half g_tup16[(size_t)2 * T_SEQ * N_TOT * TPAD]; // [dir][t][n][232]
__device__ float g_repre[N_TOT * HID];
__device__ float g_sen_s[NBAG * HID];
__device__ float g_loss_part[NBAG];
__device__ unsigned int g_bars[32];

// ---------------- ptx helpers ----------------
__device__ __forceinline__ uint32_t smem_u32(const void *p) {
    uint32_t a;
    asm("{ .reg .u64 t; cvta.to.shared.u64 t, %1; cvt.u32.u64 %0, t; }" : "=r"(a) : "l"(p));
    return a;
}
#define BULK_G2S(dst, src, bytes, mbar)                                               \
    asm volatile(                                                                     \
        "cp.async.bulk.shared::cluster.global.mbarrier::complete_tx::bytes "          \
        "[%0], [%1], %2, [%3];"                                                       \
        :: "r"((uint32_t)(dst)), "l"(src), "r"((uint32_t)(bytes)),                    \
           "r"((uint32_t)(mbar)) : "memory")
#define MBARRIER_INIT(mb, cnt) \
    asm volatile("mbarrier.init.shared.b64 [%0], %1;" :: "r"((uint32_t)(mb)), "r"((uint32_t)(cnt)) : "memory")
#define MBARRIER_EXPECT_TX(mb, tx) \
    asm volatile("mbarrier.arrive.expect_tx.shared.b64 _, [%0], %1;" :: "r"((uint32_t)(mb)), "r"((uint32_t)(tx)) : "memory")
#define MBARRIER_ARRIVE(mb) \
    asm volatile("mbarrier.arrive.shared.b64 _, [%0];" :: "r"((uint32_t)(mb)) : "memory")
#define FENCE_ASYNC_SHARED() asm volatile("fence.proxy.async.shared::cta;" ::: "memory")
#define MBARRIER_WAIT_PARITY(mb, ph) do {                                             \
    uint32_t _m = (uint32_t)(mb); uint32_t _p = (uint32_t)(ph); uint32_t _d;          \
    asm volatile("{\n\t.reg .pred p;\n\t"                                             \
        "mbarrier.try_wait.parity.acquire.cta.shared::cta.b64 p, [%1], %2;\n\t"       \
        "selp.b32 %0, 1, 0, p;\n\t}" : "=r"(_d) : "r"(_m), "r"(_p) : "memory");       \
    if (!_d) {                                                                        \
        asm volatile("{\n\t.reg .pred P1;\n\t"                                        \
            "WL_%=:\n\t"                                                              \
            "mbarrier.try_wait.parity.acquire.cta.shared::cta.b64 P1, [%0], %1, 0x989680;\n\t" \
            "@P1 bra.uni WD_%=;\n\tbra.uni WL_%=;\n\tWD_%=:\n\t}"                     \
            :: "r"(_m), "r"(_p) : "memory");                                          \
    }                                                                                 \
} while (0)
#define LDSM4(r, a)                                                                   \
    asm volatile("ldmatrix.sync.aligned.m8n8.x4.shared.b16 {%0,%1,%2,%3}, [%4];"      \
                 : "=r"((r)[0]), "=r"((r)[1]), "=r"((r)[2]), "=r"((r)[3]) : "r"(a))
#define MMA16816H(c, a, b0, b1)                                                       \
    asm volatile("mma.sync.aligned.m16n8k16.row.col.f32.f16.f16.f32 "                 \
                 "{%0,%1,%2,%3},{%4,%5,%6,%7},{%8,%9},{%0,%1,%2,%3};"                 \
                 : "+f"((c)[0]), "+f"((c)[1]), "+f"((c)[2]), "+f"((c)[3])             \
                 : "r"((a)[0]), "r"((a)[1]), "r"((a)[2]), "r"((a)[3]), "r"(b0), "r"(b1))

__device__ __forceinline__ uint32_t pack2h(__half a, __half b) {
    unsigned short ra = *(unsigned short *)&a, rb = *(unsigned short *)&b;
    return (uint32_t)ra | ((uint32_t)rb << 16);
}
__device__ __forceinline__ uint32_t swz(int row, int seg) {
    return (uint32_t)row * 64u + (uint32_t)((seg ^ ((row >> 1) & 3)) << 4);
}
__device__ __forceinline__ uint32_t swz_elem(int row, int kc) {
    return (swz(row, kc >> 3) + (uint32_t)(kc & 7) * 2u) >> 1;
}
__device__ __forceinline__ float fsigmoid(float x) {
    return __fdividef(1.f, 1.f + __expf(-x));
}
__device__ __forceinline__ float ftanh(float x) {
    x = fminf(fmaxf(x, -15.f), 15.f);
    float e = __expf(2.f * x);
    return __fdividef(e - 1.f, e + 1.f);
}

// ---------------- prep kernels ----------------
__global__ void zero_kernel() {
    size_t i = (size_t)blockIdx.x * blockDim.x + threadIdx.x;
    size_t nh = (size_t)2 * 2 * 8 * N_TOT * 32 / 2;
    if (i < nh) ((uint32_t *)g_hbf)[i] = 0u;
    if (i < 32) g_bars[i] = 0u;
}

// weights -> [dir][jt(4)][chunk(10)] contiguous 12288B swizzled fp16; row = j_local*3+gate
__global__ void prep_w_kernel(const float *__restrict__ Wihf, const float *__restrict__ Whhf,
                              const float *__restrict__ Wihb, const float *__restrict__ Whhb) {
    int idx = blockIdx.x * blockDim.x + threadIdx.x;
    if (idx >= 2 * 4 * 10 * 192 * 32) return;
    int kc = idx & 31;
    int r = (idx >> 5) % 192;
    int rest = idx / (192 * 32);
    int c = rest % 10;
    int jt = (rest / 10) & 3;
    int dir = rest / 40;
    const float *Wih = dir ? Wihb : Wihf;
    const float *Whh = dir ? Whhb : Whhf;
    int j = jt * 64 + r / 3;
    int g = r % 3;
    float v = 0.f;
    if (j < HID) {
        if (c < 2) {
            int k = c * 32 + kc;
            if (k < DIN) v = Wih[(g * HID + j) * DIN + k];
        } else {
            int kh = (c - 2) * 32 + kc;
            if (kh < HID) v = Whh[(g * HID + j) * HID + kh];
        }
    }
    uint32_t off = swz_elem(r, kc);
    g_Wt[((size_t)(dir * 4 + jt) * 10 + c) * (192 * 32) + off] = __float2half(v);
}

__global__ void gather_kernel(const int *__restrict__ sent, const int *__restrict__ p1,
                              const int *__restrict__ p2, const float *__restrict__ wemb,
                              const float *__restrict__ p1t, const float *__restrict__ p2t) {
    size_t idx = (size_t)blockIdx.x * blockDim.x + threadIdx.x;
    if (idx >= (size_t)N_TOT * T_SEQ * 64) return;
    int k = (int)(idx & 63);
    size_t nt = idx >> 6;
    int t = (int)(nt % T_SEQ);
    int n = (int)(nt / T_SEQ);
    float v = 0.f;
    if (k < EMB_W) v = wemb[(size_t)sent[n * T_SEQ + t] * EMB_W + k];
    else if (k < EMB_W + 5) v = p1t[p1[n * T_SEQ + t] * 5 + (k - EMB_W)];
    else if (k < DIN) v = p2t[p2[n * T_SEQ + t] * 5 + (k - EMB_W - 5)];
    int chunk = k >> 5, kc = k & 31;
    uint32_t off = swz_elem(n, kc);
    g_embsp[((size_t)t * 2 + chunk) * (N_TOT * 32) + off] = __float2half(v);
}

// ---------------- persistent GRU ----------------
__global__ void __launch_bounds__(NTHREADS, 1) gru_persistent_kernel(
    const float *__restrict__ bihf, const float *__restrict__ bhhf,
    const float *__restrict__ bihb, const float *__restrict__ bhhb) {
    extern __shared__ char dsm[];
    const int mtile = blockIdx.x & 15;
    const int jt = (blockIdx.x >> 4) & 3;
    const int dir = blockIdx.x >> 6;
    const int grp = (dir << 4) | mtile;
    const int n0 = mtile * 128;
    const int tid = threadIdx.x;
    const int lane = tid & 31, wid = tid >> 5;
    const int warpM = wid & 3, warpN = wid >> 2;
    const float *bih = dir ? bihb : bihf;
    const float *bhh = dir ? bhhb : bhhf;

    const uint32_t base = smem_u32(dsm);
    float *dumpIN = (float *)(dsm + DUMP_OFF);
    float *hP = (float *)(dsm + HP_OFF);        // persistent fp32 h [64 jl][128 n]
    __shared__ float bs[4][64];
    __shared__ __align__(8) unsigned long long mbar[6];
    const uint32_t mbF = smem_u32(mbar);
    const uint32_t mbE = mbF + 24;

    if (tid < 64) {
        int j = jt * 64 + tid;
        bool ok = j < HID;
        bs[0][tid] = ok ? (bih[j] + bhh[j]) : 0.f;
        bs[1][tid] = ok ? (bih[HID + j] + bhh[HID + j]) : 0.f;
        bs[2][tid] = ok ? bih[2 * HID + j] : 0.f;
        bs[3][tid] = ok ? bhh[2 * HID + j] : 0.f;
    }
#pragma unroll
    for (int it = 0; it < 16; it++) hP[it * NTHREADS + tid] = 0.f;
    if (tid == 0) {
        MBARRIER_INIT(mbF, 1);
        MBARRIER_INIT(mbF + 8, 1);
        MBARRIER_INIT(mbF + 16, 1);
        MBARRIER_INIT(mbE, 16);
        MBARRIER_INIT(mbE + 8, 16);
        MBARRIER_INIT(mbE + 16, 16);
        FENCE_ASYNC_SHARED();
    }
    __syncthreads();

    const __half *wbase = g_Wt + (size_t)(dir * 4 + jt) * 10 * (192 * 32);

    auto arm = [&](int q) {
        if (q >= 3) MBARRIER_WAIT_PARITY(mbE + (uint32_t)(q % 3) * 8, ((q / 3) + 1) & 1);
        int sp = q / 10, c = q % 10;
        int tp = dir ? (T_SEQ - 1 - sp) : sp;
        int bufin = sp & 1;
        uint32_t st = base + (uint32_t)(q % 3) * STAGE_B;
        uint32_t mb = mbF + (uint32_t)(q % 3) * 8;
        MBARRIER_EXPECT_TX(mb, STAGE_B);
        const __half *Ap;
        if (c < 2)
            Ap = g_embsp + ((size_t)tp * 2 + c) * (N_TOT * 32) + (size_t)n0 * 32;
        else
            Ap = g_hbf + (((size_t)(bufin * 2 + dir)) * 8 + (c - 2)) * (N_TOT * 32) + (size_t)n0 * 32;
        BULK_G2S(st, Ap, 8192, mb);
        BULK_G2S(st + B_OFF, wbase + (size_t)c * (192 * 32), 12288, mb);
    };

    if (tid == 0) { arm(0); arm(1); arm(2); }

    const int laneR = lane & 15;
    const int laneHi = lane >> 4;
    const int gr = lane >> 2, lc = lane & 3;

    uint32_t ah[2][2][4];
    auto ldsmA = [&](int buf, int q, int ks) {
        uint32_t sA = base + (uint32_t)(q % 3) * STAGE_B;
#pragma unroll
        for (int mi = 0; mi < 2; mi++) {
            int row = warpM * 32 + mi * 16 + laneR;
            LDSM4(ah[buf][mi], sA + swz(row, ks * 2 + laneHi));
        }
    };

    for (int s = 0; s < T_SEQ; s++) {
        const int t = dir ? (T_SEQ - 1 - s) : s;
        const int bufo = (s + 1) & 1;
        const int qb = s * 10;

        float acc[2][6][4];
#pragma unroll
        for (int mi = 0; mi < 2; mi++)
#pragma unroll
            for (int ni = 0; ni < 6; ni++)
#pragma unroll
                for (int q = 0; q < 4; q++) acc[mi][ni][q] = 0.f;

        MBARRIER_WAIT_PARITY(mbF + (uint32_t)(qb % 3) * 8, (qb / 3) & 1);
        ldsmA(0, qb, 0);
#pragma unroll
        for (int g = 0; g < 20; g++) {
            const int c = g >> 1, ks = g & 1;
            const int q = qb + c;
            const int buf = g & 1;
            uint32_t bq[3][4];
            {
                uint32_t sB = base + (uint32_t)(q % 3) * STAGE_B + B_OFF;
#pragma unroll
                for (int np = 0; np < 3; np++) {
                    int row = warpN * 48 + np * 16 + laneR;
                    LDSM4(bq[np], sB + swz(row, ks * 2 + laneHi));
                }
            }
            if (g < 19) {
                const int gn = g + 1, ksn = gn & 1;
                const int qn = qb + (gn >> 1);
                if (ksn == 0) MBARRIER_WAIT_PARITY(mbF + (uint32_t)(qn % 3) * 8, (qn / 3) & 1);
                ldsmA(buf ^ 1, qn, ksn);
            }
            // 12 MMAs; each acc updated once per stage
#pragma unroll
            for (int np = 0; np < 3; np++) {
#pragma unroll
                for (int mi = 0; mi < 2; mi++) {
                    MMA16816H(acc[mi][np * 2], ah[buf][mi], bq[np][0], bq[np][2]);
                    MMA16816H(acc[mi][np * 2 + 1], ah[buf][mi], bq[np][1], bq[np][3]);
                }
            }
            if (ks == 1) {
                if (lane == 0) MBARRIER_ARRIVE(mbE + (uint32_t)(q % 3) * 8);
                if (tid == 0 && c + 3 < 10) arm(q + 3);
            }
            if (g == 3) {
                // emb phase done: move i_n slots (col%3==2) to dumpIN, zero them
#pragma unroll
                for (int mi = 0; mi < 2; mi++)
#pragma unroll
                    for (int ni = 0; ni < 6; ni++)
#pragma unroll
                        for (int b = 0; b < 2; b++) {
                            int col = warpN * 48 + ni * 8 + lc * 2 + b;
                            if (col % 3 == 2) {
                                int jl = col / 3;
                                int m0 = warpM * 32 + mi * 16 + gr;
                                dumpIN[jl * 132 + m0] = acc[mi][ni][b];
                                dumpIN[jl * 132 + m0 + 8] = acc[mi][ni][b + 2];
                                acc[mi][ni][b] = 0.f;
                                acc[mi][ni][b + 2] = 0.f;
                            }
                        }
            }
        }

        __syncthreads();
        float *D2 = (float *)dsm;   // [192 col][132]
#pragma unroll
        for (int mi = 0; mi < 2; mi++)
#pragma unroll
            for (int ni = 0; ni < 6; ni++) {
                int col0 = warpN * 48 + ni * 8 + lc * 2;
                int m0 = warpM * 32 + mi * 16 + gr;
                D2[col0 * 132 + m0] = acc[mi][ni][0];
                D2[(col0 + 1) * 132 + m0] = acc[mi][ni][1];
                D2[col0 * 132 + m0 + 8] = acc[mi][ni][2];
                D2[(col0 + 1) * 132 + m0 + 8] = acc[mi][ni][3];
            }
        __syncthreads();

        // gates: h persistent in smem
        {
            int jl = tid >> 3, nseg = tid & 7;
            int nb = nseg * 16;
            float br = bs[0][jl], bz = bs[1][jl], bin = bs[2][jl], bhn = bs[3][jl];
            const float *Dr = D2 + (jl * 3 + 0) * 132 + nb;
            const float *Dz = D2 + (jl * 3 + 1) * 132 + nb;
            const float *Dn = D2 + (jl * 3 + 2) * 132 + nb;
            const float *Di = dumpIN + jl * 132 + nb;
            float *hp = hP + jl * 128 + nb;
            float hv[16];
#pragma unroll
            for (int i = 0; i < 16; i++) {
                float r = fsigmoid(Dr[i] + br);
                float z = fsigmoid(Dz[i] + bz);
                float nn = ftanh(Di[i] + bin + r * (Dn[i] + bhn));
                float h = (1.f - z) * nn + z * hp[i];
                hv[i] = h;
            }
#pragma unroll
            for (int i = 0; i < 16; i++) hp[i] = hv[i];
#pragma unroll
            for (int i = 0; i < 16; i++) D2[(jl * 3) * 132 + nb + i] = hv[i];
        }
        __syncthreads();

        // writeout: tup fp16 [dir][t][n][232] + hbf fp16 chunk-major (same packed data)
        {
            __half *tupp = g_tup16 + (((size_t)dir * T_SEQ + t) * N_TOT) * TPAD;
#pragma unroll
            for (int it = 0; it < 2; it++) {
                int l = it * NTHREADS + tid;
                int nl = l >> 3, seg8 = l & 7;
                int n = n0 + nl;
                int jb = seg8 * 8;
                float v[8];
#pragma unroll
                for (int q = 0; q < 8; q++) v[q] = D2[((jb + q) * 3) * 132 + nl];
                __half hh[8];
#pragma unroll
                for (int q = 0; q < 8; q++) hh[q] = __float2half(v[q]);
                uint4 vh;
                vh.x = pack2h(hh[0], hh[1]); vh.y = pack2h(hh[2], hh[3]);
                vh.z = pack2h(hh[4], hh[5]); vh.w = pack2h(hh[6], hh[7]);
                *(uint4 *)(tupp + (size_t)n * TPAD + jt * 64 + jb) = vh;
                int hch = jt * 2 + (seg8 >> 2);
                uint32_t off = swz(n, seg8 & 3);
                __half *hb0 = g_hbf + (((size_t)(bufo * 2 + dir)) * 8 + hch) * (N_TOT * 32);
                *(uint4 *)((char *)hb0 + off) = vh;
            }
        }

        // ---- group barrier (4 CTAs sharing (mtile,dir)), then arm next step ----
        if (s + 1 < T_SEQ) {
            __threadfence();
            __syncthreads();
            if (tid == 0) {
                unsigned target = 4u * (unsigned)(s + 1);
                atomicAdd(&g_bars[grp], 1u);
                while (*((volatile unsigned int *)&g_bars[grp]) < target) {
                    __nanosleep(32);
                }
            }
            __syncthreads();
            __threadfence();
            if (tid == 0) {
                arm(qb + 10);
                arm(qb + 11);
                arm(qb + 12);
            }
        }
    }
}

// ---------------- word-level attention: one warp per sentence ----------------
__global__ void __launch_bounds__(256) attn_kernel(const float *__restrict__ att_w) {
    const int n = (blockIdx.x * 256 + threadIdx.x) >> 5;
    const int lane = threadIdx.x & 31;
    const int j0 = lane * 8;
    const bool live = (lane < 29);

    float w[8];
#pragma unroll
    for (int q = 0; q < 8; q++) {
        int j = j0 + q;
        w[q] = (j < HID) ? att_w[j] : 0.f;
    }
    float acc[8];
#pragma unroll
    for (int q = 0; q < 8; q++) acc[q] = 0.f;
    float m = -1e30f, denom = 0.f;

    const __half *t0 = g_tup16 + ((size_t)0 * T_SEQ * N_TOT + n) * TPAD + j0;
    const __half *t1 = g_tup16 + ((size_t)T_SEQ * N_TOT + (size_t)n) * TPAD + j0;

    for (int t = 0; t < T_SEQ; t++) {
        float xs[8];
        if (live) {
            uint4 v0 = *(const uint4 *)(t0 + (size_t)t * N_TOT * TPAD);
            uint4 v1 = *(const uint4 *)(t1 + (size_t)t * N_TOT * TPAD);
            const __half *h0 = (const __half *)&v0;
            const __half *h1 = (const __half *)&v1;
#pragma unroll
            for (int q = 0; q < 8; q++) xs[q] = __half2float(h0[q]) + __half2float(h1[q]);
        } else {
#pragma unroll
            for (int q = 0; q < 8; q++) xs[q] = 0.f;
        }
        float part = 0.f;
#pragma unroll
        for (int q = 0; q < 8; q++) part += ftanh(xs[q]) * w[q];
#pragma unroll
        for (int o = 16; o > 0; o >>= 1) part += __shfl_xor_sync(0xffffffffu, part, o);
        float mn = fmaxf(m, part);
        float cc = __expf(m - mn), e = __expf(part - mn);
        denom = denom * cc + e;
#pragma unroll
        for (int q = 0; q < 8; q++) acc[q] = acc[q] * cc + e * xs[q];
        m = mn;
    }
    if (live) {
        float inv = __fdividef(1.f, denom);
#pragma unroll
        for (int q = 0; q < 8; q++) {
            int j = j0 + q;
            if (j < HID) g_repre[n * HID + j] = ftanh(acc[q] * inv);
        }
    }
}

// ---------------- bag attention ----------------
__global__ void __launch_bounds__(256) bag_kernel(const float *__restrict__ sen_a,
                                                  const float *__restrict__ sen_r) {
    const int b = blockIdx.x;
    const int tid = threadIdx.x;
    __shared__ float R[BAGSZ][HID];
    __shared__ float sv[BAGSZ];
    __shared__ float alpha[BAGSZ];
    for (int l = tid; l < BAGSZ * HID; l += 256) {
        int i = l / HID, j = l % HID;
        R[i][j] = g_repre[(b * BAGSZ + i) * HID + j];
    }
    __syncthreads();
    int wid = tid >> 5, lane = tid & 31;
    for (int i = wid; i < BAGSZ; i += 8) {
        float p = 0.f;
        for (int j = lane; j < HID; j += 32) p += R[i][j] * sen_a[j] * sen_r[j];
#pragma unroll
        for (int o = 16; o > 0; o >>= 1) p += __shfl_down_sync(0xffffffffu, p, o);
        if (lane == 0) sv[i] = p;
    }
    __syncthreads();
    if (tid == 0) {
        float mm = -1e30f;
        for (int i = 0; i < BAGSZ; i++) mm = fmaxf(mm, sv[i]);
        float ss = 0.f;
        for (int i = 0; i < BAGSZ; i++) { float e = expf(sv[i] - mm); alpha[i] = e; ss += e; }
        for (int i = 0; i < BAGSZ; i++) alpha[i] /= ss;
    }
    __syncthreads();
    for (int j = tid; j < HID; j += 256) {
        float a = 0.f;
#pragma unroll 4
        for (int i = 0; i < BAGSZ; i++) a += alpha[i] * R[i][j];
        g_sen_s[b * HID + j] = a;
    }
}

// ---------------- logits / prob / bce / acc ----------------
__global__ void __launch_bounds__(128) logits_kernel(const float *__restrict__ rel,
                                                     const float *__restrict__ sen_d,
                                                     const float *__restrict__ y,
                                                     float *__restrict__ out) {
    const int b = blockIdx.x;
    const int tid = threadIdx.x;
    __shared__ float ss[HID];
    __shared__ float lg[NREL];
    __shared__ float mmax;
    __shared__ int amax;
    __shared__ float dsum;
    for (int j = tid; j < HID; j += 128) ss[j] = g_sen_s[b * HID + j];
    __syncthreads();
    if (tid < NREL) {
        float a = sen_d[tid];
        const float *row = rel + (size_t)tid * HID;
        for (int j = 0; j < HID; j++) a += ss[j] * row[j];
        lg[tid] = a;
    }
    __syncthreads();
    if (tid == 0) {
        float mm = lg[0]; int am = 0;
        for (int c = 1; c < NREL; c++) if (lg[c] > mm) { mm = lg[c]; am = c; }
        mmax = mm; amax = am;
        float sum = 0.f;
        for (int c = 0; c < NREL; c++) sum += expf(lg[c] - mm);
        dsum = sum;
    }
    __syncthreads();
    if (tid < NREL) out[1 + NBAG + b * NREL + tid] = expf(lg[tid] - mmax) / dsum;
    if (tid == 0) {
        float loss = 0.f; int lab = 0;
        for (int c = 0; c < NREL; c++) {
            float l = lg[c], yv = y[b * NREL + c];
            loss += fmaxf(l, 0.f) - l * yv + log1pf(expf(-fabsf(l)));
            if (yv > 0.5f) lab = c;
        }
        g_loss_part[b] = loss / (float)NREL;
        out[1 + b] = (amax == lab) ? 1.f : 0.f;
    }
}

__global__ void loss_sum_kernel(float *__restrict__ out) {
    if (threadIdx.x == 0) {
        float s = 0.f;
        for (int b = 0; b < NBAG; b++) s += g_loss_part[b];
        out[0] = s;
    }
}

// ---------------- launch ----------------
extern "C" void kernel_launch(void *const *d_in, const int *in_sizes, int n_in,
                              void *d_out, int out_size) {
    const int *sentence = (const int *)d_in[0];
    const int *pos1 = (const int *)d_in[1];
    const int *pos2 = (const int *)d_in[2];
    const float *y_batch = (const float *)d_in[4];
    const float *word_emb = (const float *)d_in[5];
    const float *p1t = (const float *)d_in[6];
    const float *p2t = (const float *)d_in[7];
    const float *Wihf = (const float *)d_in[8];
    const float *Whhf = (const float *)d_in[9];
    const float *bihf = (const float *)d_in[10];
    const float *bhhf = (const float *)d_in[11];
    const float *Wihb = (const float *)d_in[12];
    const float *Whhb = (const float *)d_in[13];
    const float *bihb = (const float *)d_in[14];
    const float *bhhb = (const float *)d_in[15];
    const float *attw = (const float *)d_in[16];
    const float *sena = (const float *)d_in[17];
    const float *senr = (const float *)d_in[18];
    const float *rel = (const float *)d_in[19];
    const float *send = (const float *)d_in[20];
    float *out = (float *)d_out;

    cudaFuncSetAttribute(gru_persistent_kernel, cudaFuncAttributeMaxDynamicSharedMemorySize, SMEM_DYN);

    zero_kernel<<<(int)(((size_t)2 * 2 * 8 * N_TOT * 32 / 2 + 255) / 256), 256>>>();
    prep_w_kernel<<<(2 * 4 * 10 * 192 * 32 + 255) / 256, 256>>>(Wihf, Whhf, Wihb, Whhb);
    gather_kernel<<<(int)(((size_t)N_TOT * T_SEQ * 64 + 255) / 256), 256>>>(
        sentence, pos1, pos2, word_emb, p1t, p2t);

    gru_persistent_kernel<<<128, NTHREADS, SMEM_DYN>>>(bihf, bhhf, bihb, bhhb);

    attn_kernel<<<256, 256>>>(attw);
    bag_kernel<<<NBAG, 256>>>(sena, senr);
    logits_kernel<<<NBAG, 128>>>(rel, send, y_batch, out);
    loss_sum_kernel<<<1, 32>>>(out);
}